// round 9
// baseline (speedup 1.0000x reference)
#include <cuda_runtime.h>
#include <cuda_bf16.h>
#include <math.h>
#include <stdint.h>

// ---------------- problem constants ----------------
#define BB 8
#define NN 64
#define IN_DIM 16
#define EDGE_DIM 8
#define DD 128
#define HH 4
#define DHH 32
#define LL 3
#define FF 512
#define MROWS (BB*NN*NN)          // 32768
static const float INV_SCALE = 0.17677669529663687f; // 1/sqrt(32)

// ---------------- scratch (device globals; no runtime alloc) ----------------
__device__ float g_tok  [(size_t)MROWS*DD];
__device__ float g_qkv  [(size_t)MROWS*512];          // q|k|v1|v2 packed along N
__device__ float g_s    [(size_t)BB*HH*NN*NN*NN];     // [b][h][i][l][j]
// bf16 hi/lo activation copies (GEMM A operands)
__device__ __nv_bfloat16 g_tok_h[(size_t)MROWS*DD];
__device__ __nv_bfloat16 g_tok_l[(size_t)MROWS*DD];
__device__ __nv_bfloat16 g_o_h  [(size_t)MROWS*DD];
__device__ __nv_bfloat16 g_o_l  [(size_t)MROWS*DD];
__device__ __nv_bfloat16 g_hid_h[(size_t)MROWS*FF];
__device__ __nv_bfloat16 g_hid_l[(size_t)MROWS*FF];
// transposed + bf16-split weights: layout [l][N][K]
__device__ __nv_bfloat16 g_wqkvT_h[(size_t)LL*512*128];
__device__ __nv_bfloat16 g_wqkvT_l[(size_t)LL*512*128];
__device__ __nv_bfloat16 g_woT_h  [(size_t)LL*128*128];
__device__ __nv_bfloat16 g_woT_l  [(size_t)LL*128*128];
__device__ __nv_bfloat16 g_w1T_h  [(size_t)LL*512*128];
__device__ __nv_bfloat16 g_w1T_l  [(size_t)LL*512*128];
__device__ __nv_bfloat16 g_w2T_h  [(size_t)LL*128*512];
__device__ __nv_bfloat16 g_w2T_l  [(size_t)LL*128*512];
__device__ int g_mask_mode;                            // 0=int32, 1=uint8, 2=float32

// ---------------- helpers ----------------
__device__ __forceinline__ void bsplit(float v, __nv_bfloat16& h, __nv_bfloat16& l) {
    h = __float2bfloat16(v);
    l = __float2bfloat16(v - __bfloat162float(h));
}
__device__ __forceinline__ uint32_t pack2bf(__nv_bfloat16 a, __nv_bfloat16 b) {
    return (uint32_t)__bfloat16_as_ushort(a) | ((uint32_t)__bfloat16_as_ushort(b) << 16);
}
__device__ __forceinline__ uint32_t smem_u32(const void* p) {
    uint32_t a;
    asm("{ .reg .u64 t; cvta.to.shared.u64 t, %1; cvt.u32.u64 %0, t; }" : "=r"(a) : "l"(p));
    return a;
}
// D += A*B  (m16n8k16, bf16 in, f32 acc)
__device__ __forceinline__ void mma16816(float* c, const uint32_t* a, const uint32_t* b) {
    asm volatile(
        "mma.sync.aligned.m16n8k16.row.col.f32.bf16.bf16.f32 "
        "{%0,%1,%2,%3}, {%4,%5,%6,%7}, {%8,%9}, {%0,%1,%2,%3};"
        : "+f"(c[0]), "+f"(c[1]), "+f"(c[2]), "+f"(c[3])
        : "r"(a[0]), "r"(a[1]), "r"(a[2]), "r"(a[3]), "r"(b[0]), "r"(b[1]));
}
__device__ __forceinline__ void ldsm4(uint32_t addr, uint32_t* r) {
    asm volatile("ldmatrix.sync.aligned.m8n8.x4.shared.b16 {%0,%1,%2,%3}, [%4];"
        : "=r"(r[0]), "=r"(r[1]), "=r"(r[2]), "=r"(r[3]) : "r"(addr));
}
__device__ __forceinline__ void cpa16(uint32_t saddr, const void* g) {
    asm volatile("cp.async.cg.shared.global [%0], [%1], 16;" :: "r"(saddr), "l"(g));
}

// ---------------- mask dtype detector ----------------
__global__ void detect_mask_kernel(const unsigned char* __restrict__ m) {
    __shared__ int has3f, hasodd;
    if (threadIdx.x == 0) { has3f = 0; hasodd = 0; }
    __syncthreads();
    for (int i = threadIdx.x; i < 4096; i += blockDim.x) {
        unsigned char v = m[i];
        if (v == 0x3F) atomicOr(&has3f, 1);
        if (v != 0 && (i & 3)) atomicOr(&hasodd, 1);
    }
    __syncthreads();
    if (threadIdx.x == 0) g_mask_mode = has3f ? 2 : (hasodd ? 1 : 0);
}

// ---------------- merged weight transpose + bf16 split ----------------
__global__ void pack_all_kernel(const float* __restrict__ Wq, const float* __restrict__ Wk,
                                const float* __restrict__ Wv1, const float* __restrict__ Wv2,
                                const float* __restrict__ Wo, const float* __restrict__ W1,
                                const float* __restrict__ W2,
                                __nv_bfloat16* __restrict__ qh, __nv_bfloat16* __restrict__ ql,
                                __nv_bfloat16* __restrict__ oh, __nv_bfloat16* __restrict__ ol,
                                __nv_bfloat16* __restrict__ h1, __nv_bfloat16* __restrict__ l1,
                                __nv_bfloat16* __restrict__ h2, __nv_bfloat16* __restrict__ l2) {
    int blk = blockIdx.x;
    const float* src; __nv_bfloat16 *dh, *dl;
    int K, N, dstN, nOff, idx;
    if (blk < 768) {
        int seg = blk / 192;
        idx = (blk - seg*192)*256 + threadIdx.x;
        src = (seg==0)?Wq:(seg==1)?Wk:(seg==2)?Wv1:Wv2;
        dh = qh; dl = ql; K = 128; N = 128; dstN = 512; nOff = seg*128;
    } else if (blk < 960) {
        idx = (blk-768)*256 + threadIdx.x;
        src = Wo; dh = oh; dl = ol; K = 128; N = 128; dstN = 128; nOff = 0;
    } else if (blk < 1728) {
        idx = (blk-960)*256 + threadIdx.x;
        src = W1; dh = h1; dl = l1; K = 128; N = 512; dstN = 512; nOff = 0;
    } else {
        idx = (blk-1728)*256 + threadIdx.x;
        src = W2; dh = h2; dl = l2; K = 512; N = 128; dstN = 128; nOff = 0;
    }
    if (idx >= LL*N*K) return;
    int k = idx % K;
    int n = (idx / K) % N;
    int ll = idx / (K*N);
    float v = src[((size_t)ll*K + k)*N + n];
    __nv_bfloat16 vh, vl; bsplit(v, vh, vl);
    size_t o = ((size_t)ll*dstN + nOff + n)*K + k;
    dh[o] = vh; dl[o] = vl;
}

// ---------------- embedding (fp32 + hi/lo) ----------------
__global__ void embed_kernel(const float* __restrict__ x,
                             const float* __restrict__ ea,
                             const void*  __restrict__ mask,
                             const float* __restrict__ nW, const float* __restrict__ nb,
                             const float* __restrict__ eW, const float* __restrict__ eb,
                             const float* __restrict__ noe) {
    int idx = blockIdx.x;                 // b*N*N + i*N + j
    int j = idx & 63;
    int i = (idx >> 6) & 63;
    int b = idx >> 12;
    int d = threadIdx.x;                  // 0..127
    __shared__ float sx[IN_DIM];
    __shared__ float se[EDGE_DIM];
    if (threadIdx.x < IN_DIM)  sx[threadIdx.x] = x[(b*NN + i)*IN_DIM + threadIdx.x];
    if (threadIdx.x < EDGE_DIM) se[threadIdx.x] = ea[((size_t)idx)*EDGE_DIM + threadIdx.x];
    __syncthreads();
    float v;
    if (i == j) {
        v = nb[d];
        #pragma unroll
        for (int e = 0; e < IN_DIM; e++) v = fmaf(sx[e], nW[e*DD + d], v);
    } else {
        bool m;
        int mm = g_mask_mode;
        if (mm == 0)      m = ((const int*)mask)[idx] != 0;
        else if (mm == 1) m = ((const unsigned char*)mask)[idx] != 0;
        else              m = ((const float*)mask)[idx] != 0.f;
        if (m) {
            v = eb[d];
            #pragma unroll
            for (int e = 0; e < EDGE_DIM; e++) v = fmaf(se[e], eW[e*DD + d], v);
        } else {
            v = noe[d];
        }
    }
    size_t off = (size_t)idx*DD + d;
    g_tok[off] = v;
    __nv_bfloat16 vh, vl; bsplit(v, vh, vl);
    g_tok_h[off] = vh; g_tok_l[off] = vl;
}

// ================= cp.async double-buffered mma.sync bf16 GEMM =================
// 512 threads, warp grid 4x4, warp tile 32x32, K chunk 64, 2-stage pipeline.
// smem tile: 128 rows x 128B, XOR swizzle: byte = row*128 + ((c16 ^ (row&7))<<4)
#define TILE_B 16384
#define STAGE_B (4*TILE_B)
#define GSMEM (2*STAGE_B)        // 131072 bytes

__global__ __launch_bounds__(512)
void mma_gemm_kernel(const __nv_bfloat16* __restrict__ Agh,
                     const __nv_bfloat16* __restrict__ Agl,
                     const __nv_bfloat16* __restrict__ Bgh,
                     const __nv_bfloat16* __restrict__ Bgl,
                     const float* __restrict__ bias, const float* __restrict__ res,
                     const float* __restrict__ lng, const float* __restrict__ lnb,
                     float* __restrict__ Cf,
                     __nv_bfloat16* __restrict__ Ch, __nv_bfloat16* __restrict__ Cl,
                     int Kt, int Nt, int relu) {
    extern __shared__ __align__(16) char smem[];
    uint32_t smb = smem_u32(smem);
    int t   = threadIdx.x;
    int wid = t >> 5, lid = t & 31;
    int g   = lid >> 2, tg = lid & 3;
    int wm0 = (wid >> 2) * 32;           // 4 warp-rows
    int wn0 = (wid & 3) * 32;            // 4 warp-cols
    int bn  = blockIdx.x << 7;
    int bm  = blockIdx.y << 7;

    float acc[2][4][4];
    #pragma unroll
    for (int mt = 0; mt < 2; mt++)
        #pragma unroll
        for (int nt = 0; nt < 4; nt++)
            #pragma unroll
            for (int rr = 0; rr < 4; rr++) acc[mt][nt][rr] = 0.f;

    int nch = Kt >> 6;

    auto load_chunk = [&](int ch, int stg) {
        int k0 = ch << 6;
        uint32_t sb = smb + stg*STAGE_B;
        const __nv_bfloat16* srcs[4] = { Agh, Agl, Bgh, Bgl };
        #pragma unroll
        for (int tile = 0; tile < 4; tile++) {
            const __nv_bfloat16* src = srcs[tile];
            int rbase = (tile < 2) ? bm : bn;
            uint32_t tb = sb + tile*TILE_B;
            #pragma unroll
            for (int p = 0; p < 2; p++) {
                int seg = t + p*512;
                int row = seg >> 3, c16 = seg & 7;
                const __nv_bfloat16* gp = src + (size_t)(rbase + row)*Kt + k0 + c16*8;
                uint32_t sa = tb + row*128 + (((uint32_t)(c16 ^ (row & 7))) << 4);
                cpa16(sa, gp);
            }
        }
        asm volatile("cp.async.commit_group;" ::: "memory");
    };

    load_chunk(0, 0);
    for (int ch = 0; ch < nch; ch++) {
        if (ch + 1 < nch) {
            load_chunk(ch + 1, (ch + 1) & 1);
            asm volatile("cp.async.wait_group 1;" ::: "memory");
        } else {
            asm volatile("cp.async.wait_group 0;" ::: "memory");
        }
        __syncthreads();
        uint32_t sb = smb + (ch & 1)*STAGE_B;
        #pragma unroll
        for (int ks = 0; ks < 4; ks++) {
            uint32_t ah[2][4], al[2][4];
            int ac16 = ks*2 + (lid >> 4);
            #pragma unroll
            for (int mt = 0; mt < 2; mt++) {
                int row = wm0 + mt*16 + (lid & 15);
                uint32_t off = (uint32_t)(row*128) + (((uint32_t)(ac16 ^ (row & 7))) << 4);
                ldsm4(sb + off, ah[mt]);
                ldsm4(sb + TILE_B + off, al[mt]);
            }
            int bc16 = ks*2 + ((lid >> 3) & 1);
            #pragma unroll
            for (int np = 0; np < 2; np++) {
                int row = wn0 + np*16 + ((lid >> 4) & 1)*8 + (lid & 7);
                uint32_t off = (uint32_t)(row*128) + (((uint32_t)(bc16 ^ (row & 7))) << 4);
                uint32_t bh4[4], bl4[4];
                ldsm4(sb + 2*TILE_B + off, bh4);
                ldsm4(sb + 3*TILE_B + off, bl4);
                #pragma unroll
                for (int half = 0; half < 2; half++) {
                    int nt = np*2 + half;
                    #pragma unroll
                    for (int mt = 0; mt < 2; mt++) {
                        mma16816(acc[mt][nt], ah[mt], bh4 + half*2);
                        mma16816(acc[mt][nt], ah[mt], bl4 + half*2);
                        mma16816(acc[mt][nt], al[mt], bh4 + half*2);
                    }
                }
            }
        }
        __syncthreads();
    }

    // ---------------- epilogue: bias / residual / relu ----------------
    #pragma unroll
    for (int nt = 0; nt < 4; nt++) {
        int colg = bn + wn0 + nt*8 + tg*2;
        float b0 = 0.f, b1 = 0.f;
        if (bias) { b0 = bias[colg]; b1 = bias[colg+1]; }
        #pragma unroll
        for (int mt = 0; mt < 2; mt++) {
            #pragma unroll
            for (int rp = 0; rp < 2; rp++) {
                int rowg = bm + wm0 + mt*16 + rp*8 + g;
                float v0 = acc[mt][nt][rp*2]   + b0;
                float v1 = acc[mt][nt][rp*2+1] + b1;
                if (res) {
                    float2 rv = *(const float2*)(res + (size_t)rowg*Nt + colg);
                    v0 += rv.x; v1 += rv.y;
                }
                if (relu) { v0 = fmaxf(v0, 0.f); v1 = fmaxf(v1, 0.f); }
                acc[mt][nt][rp*2]   = v0;
                acc[mt][nt][rp*2+1] = v1;
            }
        }
    }

    if (lng) {
        // LN over last dim; only used with Nt==128 (4 col-warps per row).
        float* rs = (float*)smem;        // [128][4]
        float* rq = rs + 512;            // [128][4]
        #pragma unroll
        for (int mt = 0; mt < 2; mt++) {
            #pragma unroll
            for (int rp = 0; rp < 2; rp++) {
                float s = 0.f, q = 0.f;
                #pragma unroll
                for (int nt = 0; nt < 4; nt++) {
                    float v0 = acc[mt][nt][rp*2], v1 = acc[mt][nt][rp*2+1];
                    s += v0 + v1;
                    q += v0*v0 + v1*v1;
                }
                s += __shfl_xor_sync(0xffffffffu, s, 1);
                s += __shfl_xor_sync(0xffffffffu, s, 2);
                q += __shfl_xor_sync(0xffffffffu, q, 1);
                q += __shfl_xor_sync(0xffffffffu, q, 2);
                if (tg == 0) {
                    int row = wm0 + mt*16 + rp*8 + g;
                    rs[row*4 + (wid & 3)] = s;
                    rq[row*4 + (wid & 3)] = q;
                }
            }
        }
        __syncthreads();
        #pragma unroll
        for (int mt = 0; mt < 2; mt++) {
            #pragma unroll
            for (int rp = 0; rp < 2; rp++) {
                int row = wm0 + mt*16 + rp*8 + g;
                float s = rs[row*4] + rs[row*4+1] + rs[row*4+2] + rs[row*4+3];
                float q = rq[row*4] + rq[row*4+1] + rq[row*4+2] + rq[row*4+3];
                float mean = s * 0.0078125f;
                float rstd = rsqrtf(q * 0.0078125f - mean*mean + 1e-5f);
                size_t rowoff = (size_t)(bm + row)*Nt;
                #pragma unroll
                for (int nt = 0; nt < 4; nt++) {
                    int col = wn0 + nt*8 + tg*2;
                    float2 gg = *(const float2*)(lng + col);
                    float2 gb = *(const float2*)(lnb + col);
                    float v0 = (acc[mt][nt][rp*2]   - mean)*rstd*gg.x + gb.x;
                    float v1 = (acc[mt][nt][rp*2+1] - mean)*rstd*gg.y + gb.y;
                    *(float2*)(Cf + rowoff + bn + col) = make_float2(v0, v1);
                    __nv_bfloat16 h0,l0,h1,l1;
                    bsplit(v0,h0,l0); bsplit(v1,h1,l1);
                    *(uint32_t*)(Ch + rowoff + bn + col) = pack2bf(h0,h1);
                    *(uint32_t*)(Cl + rowoff + bn + col) = pack2bf(l0,l1);
                }
            }
        }
    } else {
        #pragma unroll
        for (int mt = 0; mt < 2; mt++) {
            #pragma unroll
            for (int rp = 0; rp < 2; rp++) {
                int rowg = bm + wm0 + mt*16 + rp*8 + g;
                size_t rowoff = (size_t)rowg*Nt;
                #pragma unroll
                for (int nt = 0; nt < 4; nt++) {
                    int colg = bn + wn0 + nt*8 + tg*2;
                    float v0 = acc[mt][nt][rp*2], v1 = acc[mt][nt][rp*2+1];
                    if (Cf) *(float2*)(Cf + rowoff + colg) = make_float2(v0, v1);
                    if (Ch) {
                        __nv_bfloat16 h0,l0,h1,l1;
                        bsplit(v0,h0,l0); bsplit(v1,h1,l1);
                        *(uint32_t*)(Ch + rowoff + colg) = pack2bf(h0,h1);
                        *(uint32_t*)(Cl + rowoff + colg) = pack2bf(l0,l1);
                    }
                }
            }
        }
    }
}

// ---------------- scores: s[b,h,i,l,j] = (1/SCALE) * q[b,i,l,h,:] . k[b,l,j,h,:] ------
__global__ __launch_bounds__(256)
void score_kernel() {
    int bid = blockIdx.x;                  // bh*64 + l
    int l  = bid & 63;
    int bh = bid >> 6;
    int h  = bh & 3;
    int b  = bh >> 2;
    __shared__ float Qs[64][33];
    __shared__ float Ks[64][33];
    int t = threadIdx.x;
    for (int idx = t; idx < 64*32; idx += 256) {
        int r = idx >> 5, c = idx & 31;
        Qs[r][c] = g_qkv[((size_t)((b*NN + r)*NN + l))*512 +       h*DHH + c]; // q, r=i
        Ks[r][c] = g_qkv[((size_t)((b*NN + l)*NN + r))*512 + 128 + h*DHH + c]; // k, r=j
    }
    __syncthreads();
    int tj = t & 15, ti = t >> 4;
    float acc[4][4] = {};
    #pragma unroll
    for (int c = 0; c < 32; c++) {
        float q[4], k[4];
        #pragma unroll
        for (int u = 0; u < 4; u++) { q[u] = Qs[ti*4+u][c]; k[u] = Ks[tj*4+u][c]; }
        #pragma unroll
        for (int i2 = 0; i2 < 4; i2++)
            #pragma unroll
            for (int j2 = 0; j2 < 4; j2++)
                acc[i2][j2] = fmaf(q[i2], k[j2], acc[i2][j2]);
    }
    #pragma unroll
    for (int i2 = 0; i2 < 4; i2++) {
        int i = ti*4 + i2;
        float4 v = make_float4(acc[i2][0]*INV_SCALE, acc[i2][1]*INV_SCALE,
                               acc[i2][2]*INV_SCALE, acc[i2][3]*INV_SCALE);
        *(float4*)(g_s + ((size_t)(bh*NN + i)*NN + l)*NN + tj*4) = v;
    }
}

// ---------------- fused softmax + tiled attn_o ----------------
// block = (b, h, i-tile 16, j-tile 16). s tile [l=64][i=16][j=16] in smem,
// 2-pass softmax over l in-place, then l-chunk contraction.
#define FA_S  0                               // 16384 floats
#define FA_V1 16384                           // [i][l][36]
#define FA_V2 (16384 + 16*16*36)              // [l][j][36]
#define FATTN_SMEM ((16384 + 2*16*16*36)*4)   // 139264 B

__global__ __launch_bounds__(256)
void attn_o_kernel() {
    extern __shared__ __align__(16) float sm[];
    float* s_t = sm + FA_S;
    float* v1s = sm + FA_V1;
    float* v2s = sm + FA_V2;
    int bx = blockIdx.x;
    int jt = bx & 3;
    int it = (bx >> 2) & 3;
    int h  = (bx >> 4) & 3;
    int b  = bx >> 6;
    int bh = b*HH + h;
    int i0 = it*16, j0 = jt*16;
    int t = threadIdx.x;
    int ti = t >> 4, tj = t & 15;

    // ---- load full s tile [l][i][j] ----
    #pragma unroll
    for (int k = 0; k < 16; k++) {
        int fid = t + k*256;                 // 0..4095 float4s
        int jq = fid & 3, i_ = (fid >> 2) & 15, l_ = fid >> 6;
        float4 v = *(const float4*)(g_s +
            ((size_t)(bh*NN + i0 + i_)*NN + l_)*NN + j0 + jq*4);
        *(float4*)(s_t + (l_*16 + i_)*16 + jq*4) = v;
    }
    __syncthreads();

    // ---- softmax over l for this thread's (ti, tj) column ----
    {
        float mx = -1e30f;
        #pragma unroll 8
        for (int l = 0; l < 64; l++) mx = fmaxf(mx, s_t[(l*16 + ti)*16 + tj]);
        float s = 0.f;
        #pragma unroll 8
        for (int l = 0; l < 64; l++) {
            float e = __expf(s_t[(l*16 + ti)*16 + tj] - mx);
            s_t[(l*16 + ti)*16 + tj] = e;
            s += e;
        }
        float inv = 1.f / s;
        #pragma unroll 8
        for (int l = 0; l < 64; l++) s_t[(l*16 + ti)*16 + tj] *= inv;
    }
    __syncthreads();

    float acc[32];
    #pragma unroll
    for (int d = 0; d < 32; d++) acc[d] = 0.f;

    for (int lc = 0; lc < 4; lc++) {
        int l0 = lc*16;
        #pragma unroll
        for (int k = 0; k < 8; k++) {
            int fid = t + k*256;
            int dq = fid & 7, l = (fid >> 3) & 15, i_ = fid >> 7;
            float4 v = *(const float4*)(g_qkv +
                ((size_t)((b*NN + i0 + i_)*NN + l0 + l))*512 + 256 + h*DHH + dq*4);
            *(float4*)(v1s + (i_*16 + l)*36 + dq*4) = v;
        }
        #pragma unroll
        for (int k = 0; k < 8; k++) {
            int fid = t + k*256;
            int dq = fid & 7, j_ = (fid >> 3) & 15, l_ = fid >> 7;
            float4 v = *(const float4*)(g_qkv +
                ((size_t)((b*NN + l0 + l_)*NN + j0 + j_))*512 + 384 + h*DHH + dq*4);
            *(float4*)(v2s + (l_*16 + j_)*36 + dq*4) = v;
        }
        __syncthreads();
        #pragma unroll 4
        for (int l = 0; l < 16; l++) {
            float a = s_t[((l0 + l)*16 + ti)*16 + tj];
            const float* p1 = v1s + (ti*16 + l)*36;
            const float* p2 = v2s + (l*16 + tj)*36;
            #pragma unroll
            for (int dq = 0; dq < 8; dq++) {
                float4 x = *(const float4*)(p1 + dq*4);
                float4 y = *(const float4*)(p2 + dq*4);
                acc[dq*4+0] = fmaf(a, x.x * y.x, acc[dq*4+0]);
                acc[dq*4+1] = fmaf(a, x.y * y.y, acc[dq*4+1]);
                acc[dq*4+2] = fmaf(a, x.z * y.z, acc[dq*4+2]);
                acc[dq*4+3] = fmaf(a, x.w * y.w, acc[dq*4+3]);
            }
        }
        __syncthreads();
    }
    size_t obase = ((size_t)((b*NN + i0 + ti)*NN + j0 + tj) << 7) + h*DHH;
    #pragma unroll
    for (int dq = 0; dq < 8; dq++) {
        __nv_bfloat16 h0,l0_,h1,l1,h2,l2,h3,l3;
        bsplit(acc[dq*4+0],h0,l0_); bsplit(acc[dq*4+1],h1,l1);
        bsplit(acc[dq*4+2],h2,l2);  bsplit(acc[dq*4+3],h3,l3);
        *(uint2*)(g_o_h + obase + dq*4) = make_uint2(pack2bf(h0,h1), pack2bf(h2,h3));
        *(uint2*)(g_o_l + obase + dq*4) = make_uint2(pack2bf(l0_,l1), pack2bf(l2,l3));
    }
}

// ---------------- final: out[b,n] = diag_tok . Wout + bout ----------------
__global__ __launch_bounds__(128)
void out_kernel(const float* __restrict__ Wout, const float* __restrict__ bout,
                float* __restrict__ out) {
    int bn = blockIdx.x;             // b*64 + n
    int n = bn & 63;
    int d = threadIdx.x;
    float v = g_tok[((size_t)bn*NN + n)*DD + d] * Wout[d];
    __shared__ float r[4];
    #pragma unroll
    for (int o = 16; o > 0; o >>= 1) v += __shfl_xor_sync(0xffffffffu, v, o);
    if ((d & 31) == 0) r[d >> 5] = v;
    __syncthreads();
    if (d == 0) out[bn] = r[0] + r[1] + r[2] + r[3] + bout[0];
}

// ---------------- host driver ----------------
extern "C" void kernel_launch(void* const* d_in, const int* in_sizes, int n_in,
                              void* d_out, int out_size) {
    const float* x    = (const float*)d_in[0];
    const float* ea   = (const float*)d_in[1];
    const void*  mask = d_in[2];
    const float* nW   = (const float*)d_in[3];
    const float* nb   = (const float*)d_in[4];
    const float* eW   = (const float*)d_in[5];
    const float* eb   = (const float*)d_in[6];
    const float* noe  = (const float*)d_in[7];
    const float* Wq   = (const float*)d_in[8];
    const float* Wk   = (const float*)d_in[9];
    const float* Wv1  = (const float*)d_in[10];
    const float* Wv2  = (const float*)d_in[11];
    const float* Wo   = (const float*)d_in[12];
    const float* bo   = (const float*)d_in[13];
    const float* ln1g = (const float*)d_in[14];
    const float* ln1b = (const float*)d_in[15];
    const float* W1   = (const float*)d_in[16];
    const float* b1   = (const float*)d_in[17];
    const float* W2   = (const float*)d_in[18];
    const float* b2   = (const float*)d_in[19];
    const float* ln2g = (const float*)d_in[20];
    const float* ln2b = (const float*)d_in[21];
    const float* Wout = (const float*)d_in[22];
    const float* bout = (const float*)d_in[23];

    float *tok, *qkv;
    __nv_bfloat16 *tokh, *tokl, *oh_, *ol_, *hidh, *hidl;
    __nv_bfloat16 *wqkvh, *wqkvl, *woh, *wol, *w1h, *w1l, *w2h, *w2l;
    cudaGetSymbolAddress((void**)&tok,   g_tok);
    cudaGetSymbolAddress((void**)&qkv,   g_qkv);
    cudaGetSymbolAddress((void**)&tokh,  g_tok_h);
    cudaGetSymbolAddress((void**)&tokl,  g_tok_l);
    cudaGetSymbolAddress((void**)&oh_,   g_o_h);
    cudaGetSymbolAddress((void**)&ol_,   g_o_l);
    cudaGetSymbolAddress((void**)&hidh,  g_hid_h);
    cudaGetSymbolAddress((void**)&hidl,  g_hid_l);
    cudaGetSymbolAddress((void**)&wqkvh, g_wqkvT_h);
    cudaGetSymbolAddress((void**)&wqkvl, g_wqkvT_l);
    cudaGetSymbolAddress((void**)&woh,   g_woT_h);
    cudaGetSymbolAddress((void**)&wol,   g_woT_l);
    cudaGetSymbolAddress((void**)&w1h,   g_w1T_h);
    cudaGetSymbolAddress((void**)&w1l,   g_w1T_l);
    cudaGetSymbolAddress((void**)&w2h,   g_w2T_h);
    cudaGetSymbolAddress((void**)&w2l,   g_w2T_l);

    cudaFuncSetAttribute(mma_gemm_kernel,
                         cudaFuncAttributeMaxDynamicSharedMemorySize, GSMEM);
    cudaFuncSetAttribute(attn_o_kernel,
                         cudaFuncAttributeMaxDynamicSharedMemorySize, FATTN_SMEM);

    detect_mask_kernel<<<1, 256>>>((const unsigned char*)mask);
    pack_all_kernel<<<2496, 256>>>(Wq, Wk, Wv1, Wv2, Wo, W1, W2,
                                   wqkvh, wqkvl, woh, wol, w1h, w1l, w2h, w2l);
    embed_kernel<<<MROWS, DD>>>(x, ea, mask, nW, nb, eW, eb, noe);

    dim3 gN128(1, MROWS/128);
    dim3 gN512(4, MROWS/128);

    for (int l = 0; l < LL; l++) {
        const __nv_bfloat16* wqh = wqkvh + (size_t)l*512*128;
        const __nv_bfloat16* wql = wqkvl + (size_t)l*512*128;
        const __nv_bfloat16* wo_h = woh + (size_t)l*128*128;
        const __nv_bfloat16* wo_l = wol + (size_t)l*128*128;
        const __nv_bfloat16* w1_h = w1h + (size_t)l*512*128;
        const __nv_bfloat16* w1_l = w1l + (size_t)l*512*128;
        const __nv_bfloat16* w2_h = w2h + (size_t)l*128*512;
        const __nv_bfloat16* w2_l = w2l + (size_t)l*128*512;
        const float* bo_l  = bo  + (size_t)l*DD;
        const float* g1_l  = ln1g + (size_t)l*DD;
        const float* b1l_l = ln1b + (size_t)l*DD;
        const float* bf1_l = b1  + (size_t)l*FF;
        const float* bf2_l = b2  + (size_t)l*DD;
        const float* g2_l  = ln2g + (size_t)l*DD;
        const float* b2l_l = ln2b + (size_t)l*DD;

        // fused QKV projection: A = tok (split), C = qkv fp32
        mma_gemm_kernel<<<gN512, 512, GSMEM>>>(tokh, tokl, wqh, wql,
            nullptr, nullptr, nullptr, nullptr, qkv, nullptr, nullptr, 128, 512, 0);

        score_kernel<<<BB*HH*NN, 256>>>();
        attn_o_kernel<<<512, 256, FATTN_SMEM>>>();

        // o-projection + bias + residual(tok) + LN1 -> tok fp32 + split
        mma_gemm_kernel<<<gN128, 512, GSMEM>>>(oh_, ol_, wo_h, wo_l,
            bo_l, tok, g1_l, b1l_l, tok, tokh, tokl, 128, 128, 0);
        // FFN up + relu -> hid split only
        mma_gemm_kernel<<<gN512, 512, GSMEM>>>(tokh, tokl, w1_h, w1_l,
            bf1_l, nullptr, nullptr, nullptr, nullptr, hidh, hidl, 128, 512, 1);
        // FFN down + bias + residual(tok) + LN2 -> tok fp32 + split
        mma_gemm_kernel<<<gN128, 512, GSMEM>>>(hidh, hidl, w2_h, w2_l,
            bf2_l, tok, g2_l, b2l_l, tok, tokh, tokl, 512, 128, 0);
    }

    out_kernel<<<BB*NN, 128>>>(Wout, bout, (float*)d_out);
}

// round 11
// speedup vs baseline: 1.0591x; 1.0591x over previous
#include <cuda_runtime.h>
#include <cuda_bf16.h>
#include <math.h>
#include <stdint.h>

// ---------------- problem constants ----------------
#define BB 8
#define NN 64
#define IN_DIM 16
#define EDGE_DIM 8
#define DD 128
#define HH 4
#define DHH 32
#define LL 3
#define FF 512
#define MROWS (BB*NN*NN)          // 32768
static const float INV_SCALE = 0.17677669529663687f; // 1/sqrt(32)

// ---------------- scratch (device globals; no runtime alloc) ----------------
__device__ float g_tok  [(size_t)MROWS*DD];
__device__ float g_qkv  [(size_t)MROWS*512];          // q|k|v1|v2 packed along N
__device__ float g_s    [(size_t)BB*HH*NN*NN*NN];     // [b][h][i][l][j]
// bf16 hi/lo activation copies (GEMM A operands)
__device__ __nv_bfloat16 g_tok_h[(size_t)MROWS*DD];
__device__ __nv_bfloat16 g_tok_l[(size_t)MROWS*DD];
__device__ __nv_bfloat16 g_o_h  [(size_t)MROWS*DD];
__device__ __nv_bfloat16 g_o_l  [(size_t)MROWS*DD];
__device__ __nv_bfloat16 g_hid_h[(size_t)MROWS*FF];
__device__ __nv_bfloat16 g_hid_l[(size_t)MROWS*FF];
// transposed + bf16-split weights: layout [l][N][K]
__device__ __nv_bfloat16 g_wqkvT_h[(size_t)LL*512*128];
__device__ __nv_bfloat16 g_wqkvT_l[(size_t)LL*512*128];
__device__ __nv_bfloat16 g_woT_h  [(size_t)LL*128*128];
__device__ __nv_bfloat16 g_woT_l  [(size_t)LL*128*128];
__device__ __nv_bfloat16 g_w1T_h  [(size_t)LL*512*128];
__device__ __nv_bfloat16 g_w1T_l  [(size_t)LL*512*128];
__device__ __nv_bfloat16 g_w2T_h  [(size_t)LL*128*512];
__device__ __nv_bfloat16 g_w2T_l  [(size_t)LL*128*512];
__device__ int g_mask_mode;                            // 0=int32, 1=uint8, 2=float32

// ---------------- helpers ----------------
__device__ __forceinline__ void bsplit(float v, __nv_bfloat16& h, __nv_bfloat16& l) {
    h = __float2bfloat16(v);
    l = __float2bfloat16(v - __bfloat162float(h));
}
__device__ __forceinline__ uint32_t pack2bf(__nv_bfloat16 a, __nv_bfloat16 b) {
    return (uint32_t)__bfloat16_as_ushort(a) | ((uint32_t)__bfloat16_as_ushort(b) << 16);
}
__device__ __forceinline__ uint32_t smem_u32(const void* p) {
    uint32_t a;
    asm("{ .reg .u64 t; cvta.to.shared.u64 t, %1; cvt.u32.u64 %0, t; }" : "=r"(a) : "l"(p));
    return a;
}
// D += A*B  (m16n8k16, bf16 in, f32 acc)
__device__ __forceinline__ void mma16816(float* c, const uint32_t* a, const uint32_t* b) {
    asm volatile(
        "mma.sync.aligned.m16n8k16.row.col.f32.bf16.bf16.f32 "
        "{%0,%1,%2,%3}, {%4,%5,%6,%7}, {%8,%9}, {%0,%1,%2,%3};"
        : "+f"(c[0]), "+f"(c[1]), "+f"(c[2]), "+f"(c[3])
        : "r"(a[0]), "r"(a[1]), "r"(a[2]), "r"(a[3]), "r"(b[0]), "r"(b[1]));
}
__device__ __forceinline__ void ldsm4(uint32_t addr, uint32_t* r) {
    asm volatile("ldmatrix.sync.aligned.m8n8.x4.shared.b16 {%0,%1,%2,%3}, [%4];"
        : "=r"(r[0]), "=r"(r[1]), "=r"(r[2]), "=r"(r[3]) : "r"(addr));
}
__device__ __forceinline__ void cpa16(uint32_t saddr, const void* g) {
    asm volatile("cp.async.cg.shared.global [%0], [%1], 16;" :: "r"(saddr), "l"(g));
}

// ---------------- mask dtype detector ----------------
__global__ void detect_mask_kernel(const unsigned char* __restrict__ m) {
    __shared__ int has3f, hasodd;
    if (threadIdx.x == 0) { has3f = 0; hasodd = 0; }
    __syncthreads();
    for (int i = threadIdx.x; i < 4096; i += blockDim.x) {
        unsigned char v = m[i];
        if (v == 0x3F) atomicOr(&has3f, 1);
        if (v != 0 && (i & 3)) atomicOr(&hasodd, 1);
    }
    __syncthreads();
    if (threadIdx.x == 0) g_mask_mode = has3f ? 2 : (hasodd ? 1 : 0);
}

// ---------------- merged weight transpose + bf16 split ----------------
__global__ void pack_all_kernel(const float* __restrict__ Wq, const float* __restrict__ Wk,
                                const float* __restrict__ Wv1, const float* __restrict__ Wv2,
                                const float* __restrict__ Wo, const float* __restrict__ W1,
                                const float* __restrict__ W2,
                                __nv_bfloat16* __restrict__ qh, __nv_bfloat16* __restrict__ ql,
                                __nv_bfloat16* __restrict__ oh, __nv_bfloat16* __restrict__ ol,
                                __nv_bfloat16* __restrict__ h1, __nv_bfloat16* __restrict__ l1,
                                __nv_bfloat16* __restrict__ h2, __nv_bfloat16* __restrict__ l2) {
    int blk = blockIdx.x;
    const float* src; __nv_bfloat16 *dh, *dl;
    int K, N, dstN, nOff, idx;
    if (blk < 768) {
        int seg = blk / 192;
        idx = (blk - seg*192)*256 + threadIdx.x;
        src = (seg==0)?Wq:(seg==1)?Wk:(seg==2)?Wv1:Wv2;
        dh = qh; dl = ql; K = 128; N = 128; dstN = 512; nOff = seg*128;
    } else if (blk < 960) {
        idx = (blk-768)*256 + threadIdx.x;
        src = Wo; dh = oh; dl = ol; K = 128; N = 128; dstN = 128; nOff = 0;
    } else if (blk < 1728) {
        idx = (blk-960)*256 + threadIdx.x;
        src = W1; dh = h1; dl = l1; K = 128; N = 512; dstN = 512; nOff = 0;
    } else {
        idx = (blk-1728)*256 + threadIdx.x;
        src = W2; dh = h2; dl = l2; K = 512; N = 128; dstN = 128; nOff = 0;
    }
    if (idx >= LL*N*K) return;
    int k = idx % K;
    int n = (idx / K) % N;
    int ll = idx / (K*N);
    float v = src[((size_t)ll*K + k)*N + n];
    __nv_bfloat16 vh, vl; bsplit(v, vh, vl);
    size_t o = ((size_t)ll*dstN + nOff + n)*K + k;
    dh[o] = vh; dl[o] = vl;
}

// ---------------- embedding (fp32 + hi/lo) ----------------
__global__ void embed_kernel(const float* __restrict__ x,
                             const float* __restrict__ ea,
                             const void*  __restrict__ mask,
                             const float* __restrict__ nW, const float* __restrict__ nb,
                             const float* __restrict__ eW, const float* __restrict__ eb,
                             const float* __restrict__ noe) {
    int idx = blockIdx.x;                 // b*N*N + i*N + j
    int j = idx & 63;
    int i = (idx >> 6) & 63;
    int b = idx >> 12;
    int d = threadIdx.x;                  // 0..127
    __shared__ float sx[IN_DIM];
    __shared__ float se[EDGE_DIM];
    if (threadIdx.x < IN_DIM)  sx[threadIdx.x] = x[(b*NN + i)*IN_DIM + threadIdx.x];
    if (threadIdx.x < EDGE_DIM) se[threadIdx.x] = ea[((size_t)idx)*EDGE_DIM + threadIdx.x];
    __syncthreads();
    float v;
    if (i == j) {
        v = nb[d];
        #pragma unroll
        for (int e = 0; e < IN_DIM; e++) v = fmaf(sx[e], nW[e*DD + d], v);
    } else {
        bool m;
        int mm = g_mask_mode;
        if (mm == 0)      m = ((const int*)mask)[idx] != 0;
        else if (mm == 1) m = ((const unsigned char*)mask)[idx] != 0;
        else              m = ((const float*)mask)[idx] != 0.f;
        if (m) {
            v = eb[d];
            #pragma unroll
            for (int e = 0; e < EDGE_DIM; e++) v = fmaf(se[e], eW[e*DD + d], v);
        } else {
            v = noe[d];
        }
    }
    size_t off = (size_t)idx*DD + d;
    g_tok[off] = v;
    __nv_bfloat16 vh, vl; bsplit(v, vh, vl);
    g_tok_h[off] = vh; g_tok_l[off] = vl;
}

// ================= cp.async double-buffered mma.sync bf16 GEMM =================
// 512 threads, warp grid 4x4, warp tile 32x32, K chunk 64, 2-stage cp.async
// pipeline + register-level fragment double-buffering (A) per k-step.
// smem tile: 128 rows x 128B, XOR swizzle: byte = row*128 + ((c16 ^ (row&7))<<4)
#define TILE_B 16384
#define STAGE_B (4*TILE_B)
#define GSMEM (2*STAGE_B)        // 131072 bytes

__global__ __launch_bounds__(512)
void mma_gemm_kernel(const __nv_bfloat16* __restrict__ Agh,
                     const __nv_bfloat16* __restrict__ Agl,
                     const __nv_bfloat16* __restrict__ Bgh,
                     const __nv_bfloat16* __restrict__ Bgl,
                     const float* __restrict__ bias, const float* __restrict__ res,
                     const float* __restrict__ lng, const float* __restrict__ lnb,
                     float* __restrict__ Cf,
                     __nv_bfloat16* __restrict__ Ch, __nv_bfloat16* __restrict__ Cl,
                     int Kt, int Nt, int relu) {
    extern __shared__ __align__(16) char smem[];
    uint32_t smb = smem_u32(smem);
    int t   = threadIdx.x;
    int wid = t >> 5, lid = t & 31;
    int g   = lid >> 2, tg = lid & 3;
    int wm0 = (wid >> 2) * 32;           // 4 warp-rows
    int wn0 = (wid & 3) * 32;            // 4 warp-cols
    int bn  = blockIdx.x << 7;
    int bm  = blockIdx.y << 7;

    float acc[2][4][4];
    #pragma unroll
    for (int mt = 0; mt < 2; mt++)
        #pragma unroll
        for (int nt = 0; nt < 4; nt++)
            #pragma unroll
            for (int rr = 0; rr < 4; rr++) acc[mt][nt][rr] = 0.f;

    int nch = Kt >> 6;

    auto load_chunk = [&](int ch, int stg) {
        int k0 = ch << 6;
        uint32_t sb = smb + stg*STAGE_B;
        const __nv_bfloat16* srcs[4] = { Agh, Agl, Bgh, Bgl };
        #pragma unroll
        for (int tile = 0; tile < 4; tile++) {
            const __nv_bfloat16* src = srcs[tile];
            int rbase = (tile < 2) ? bm : bn;
            uint32_t tb = sb + tile*TILE_B;
            #pragma unroll
            for (int p = 0; p < 2; p++) {
                int seg = t + p*512;
                int row = seg >> 3, c16 = seg & 7;
                const __nv_bfloat16* gp = src + (size_t)(rbase + row)*Kt + k0 + c16*8;
                uint32_t sa = tb + row*128 + (((uint32_t)(c16 ^ (row & 7))) << 4);
                cpa16(sa, gp);
            }
        }
        asm volatile("cp.async.commit_group;" ::: "memory");
    };

    // fragment loaders
    auto loadA = [&](uint32_t sb, int ks, uint32_t (&ah)[2][4], uint32_t (&al)[2][4]) {
        int ac16 = ks*2 + (lid >> 4);
        #pragma unroll
        for (int mt = 0; mt < 2; mt++) {
            int row = wm0 + mt*16 + (lid & 15);
            uint32_t off = (uint32_t)(row*128) + (((uint32_t)(ac16 ^ (row & 7))) << 4);
            ldsm4(sb + off, ah[mt]);
            ldsm4(sb + TILE_B + off, al[mt]);
        }
    };
    auto loadB = [&](uint32_t sb, int ks, uint32_t (&bh)[2][4], uint32_t (&bl)[2][4]) {
        int bc16 = ks*2 + ((lid >> 3) & 1);
        #pragma unroll
        for (int np = 0; np < 2; np++) {
            int row = wn0 + np*16 + ((lid >> 4) & 1)*8 + (lid & 7);
            uint32_t off = (uint32_t)(row*128) + (((uint32_t)(bc16 ^ (row & 7))) << 4);
            ldsm4(sb + 2*TILE_B + off, bh[np]);
            ldsm4(sb + 3*TILE_B + off, bl[np]);
        }
    };

    load_chunk(0, 0);
    for (int ch = 0; ch < nch; ch++) {
        if (ch + 1 < nch) {
            load_chunk(ch + 1, (ch + 1) & 1);
            asm volatile("cp.async.wait_group 1;" ::: "memory");
        } else {
            asm volatile("cp.async.wait_group 0;" ::: "memory");
        }
        __syncthreads();
        uint32_t sb = smb + (ch & 1)*STAGE_B;

        uint32_t ahb[2][2][4], alb[2][2][4];
        loadA(sb, 0, ahb[0], alb[0]);
        #pragma unroll
        for (int ks = 0; ks < 4; ks++) {
            uint32_t bh[2][4], bl[2][4];
            loadB(sb, ks, bh, bl);                    // B frags for current ks
            if (ks < 3)
                loadA(sb, ks+1, ahb[(ks+1)&1], alb[(ks+1)&1]);  // A prefetch
            int cur = ks & 1;
            #pragma unroll
            for (int np = 0; np < 2; np++) {
                #pragma unroll
                for (int half = 0; half < 2; half++) {
                    int nt = np*2 + half;
                    #pragma unroll
                    for (int mt = 0; mt < 2; mt++) {
                        mma16816(acc[mt][nt], ahb[cur][mt], bh[np] + half*2);
                        mma16816(acc[mt][nt], ahb[cur][mt], bl[np] + half*2);
                        mma16816(acc[mt][nt], alb[cur][mt], bh[np] + half*2);
                    }
                }
            }
        }
        __syncthreads();
    }

    // ---------------- epilogue: bias / residual / relu ----------------
    #pragma unroll
    for (int nt = 0; nt < 4; nt++) {
        int colg = bn + wn0 + nt*8 + tg*2;
        float b0 = 0.f, b1 = 0.f;
        if (bias) { b0 = bias[colg]; b1 = bias[colg+1]; }
        #pragma unroll
        for (int mt = 0; mt < 2; mt++) {
            #pragma unroll
            for (int rp = 0; rp < 2; rp++) {
                int rowg = bm + wm0 + mt*16 + rp*8 + g;
                float v0 = acc[mt][nt][rp*2]   + b0;
                float v1 = acc[mt][nt][rp*2+1] + b1;
                if (res) {
                    float2 rv = *(const float2*)(res + (size_t)rowg*Nt + colg);
                    v0 += rv.x; v1 += rv.y;
                }
                if (relu) { v0 = fmaxf(v0, 0.f); v1 = fmaxf(v1, 0.f); }
                acc[mt][nt][rp*2]   = v0;
                acc[mt][nt][rp*2+1] = v1;
            }
        }
    }

    if (lng) {
        // LN over last dim; only used with Nt==128 (4 col-warps per row).
        float* rs = (float*)smem;        // [128][4]
        float* rq = rs + 512;            // [128][4]
        #pragma unroll
        for (int mt = 0; mt < 2; mt++) {
            #pragma unroll
            for (int rp = 0; rp < 2; rp++) {
                float s = 0.f, q = 0.f;
                #pragma unroll
                for (int nt = 0; nt < 4; nt++) {
                    float v0 = acc[mt][nt][rp*2], v1 = acc[mt][nt][rp*2+1];
                    s += v0 + v1;
                    q += v0*v0 + v1*v1;
                }
                s += __shfl_xor_sync(0xffffffffu, s, 1);
                s += __shfl_xor_sync(0xffffffffu, s, 2);
                q += __shfl_xor_sync(0xffffffffu, q, 1);
                q += __shfl_xor_sync(0xffffffffu, q, 2);
                if (tg == 0) {
                    int row = wm0 + mt*16 + rp*8 + g;
                    rs[row*4 + (wid & 3)] = s;
                    rq[row*4 + (wid & 3)] = q;
                }
            }
        }
        __syncthreads();
        #pragma unroll
        for (int mt = 0; mt < 2; mt++) {
            #pragma unroll
            for (int rp = 0; rp < 2; rp++) {
                int row = wm0 + mt*16 + rp*8 + g;
                float s = rs[row*4] + rs[row*4+1] + rs[row*4+2] + rs[row*4+3];
                float q = rq[row*4] + rq[row*4+1] + rq[row*4+2] + rq[row*4+3];
                float mean = s * 0.0078125f;
                float rstd = rsqrtf(q * 0.0078125f - mean*mean + 1e-5f);
                size_t rowoff = (size_t)(bm + row)*Nt;
                #pragma unroll
                for (int nt = 0; nt < 4; nt++) {
                    int col = wn0 + nt*8 + tg*2;
                    float2 gg = *(const float2*)(lng + col);
                    float2 gb = *(const float2*)(lnb + col);
                    float v0 = (acc[mt][nt][rp*2]   - mean)*rstd*gg.x + gb.x;
                    float v1 = (acc[mt][nt][rp*2+1] - mean)*rstd*gg.y + gb.y;
                    *(float2*)(Cf + rowoff + bn + col) = make_float2(v0, v1);
                    __nv_bfloat16 h0,l0,h1,l1;
                    bsplit(v0,h0,l0); bsplit(v1,h1,l1);
                    *(uint32_t*)(Ch + rowoff + bn + col) = pack2bf(h0,h1);
                    *(uint32_t*)(Cl + rowoff + bn + col) = pack2bf(l0,l1);
                }
            }
        }
    } else {
        #pragma unroll
        for (int mt = 0; mt < 2; mt++) {
            #pragma unroll
            for (int rp = 0; rp < 2; rp++) {
                int rowg = bm + wm0 + mt*16 + rp*8 + g;
                size_t rowoff = (size_t)rowg*Nt;
                #pragma unroll
                for (int nt = 0; nt < 4; nt++) {
                    int colg = bn + wn0 + nt*8 + tg*2;
                    float v0 = acc[mt][nt][rp*2], v1 = acc[mt][nt][rp*2+1];
                    if (Cf) *(float2*)(Cf + rowoff + colg) = make_float2(v0, v1);
                    if (Ch) {
                        __nv_bfloat16 h0,l0,h1,l1;
                        bsplit(v0,h0,l0); bsplit(v1,h1,l1);
                        *(uint32_t*)(Ch + rowoff + colg) = pack2bf(h0,h1);
                        *(uint32_t*)(Cl + rowoff + colg) = pack2bf(l0,l1);
                    }
                }
            }
        }
    }
}

// ---------------- scores: s[b,h,i,l,j] = (1/SCALE) * q[b,i,l,h,:] . k[b,l,j,h,:] ------
__global__ __launch_bounds__(256)
void score_kernel() {
    int bid = blockIdx.x;                  // bh*64 + l
    int l  = bid & 63;
    int bh = bid >> 6;
    int h  = bh & 3;
    int b  = bh >> 2;
    __shared__ float Qs[64][33];
    __shared__ float Ks[64][33];
    int t = threadIdx.x;
    for (int idx = t; idx < 64*32; idx += 256) {
        int r = idx >> 5, c = idx & 31;
        Qs[r][c] = g_qkv[((size_t)((b*NN + r)*NN + l))*512 +       h*DHH + c]; // q, r=i
        Ks[r][c] = g_qkv[((size_t)((b*NN + l)*NN + r))*512 + 128 + h*DHH + c]; // k, r=j
    }
    __syncthreads();
    int tj = t & 15, ti = t >> 4;
    float acc[4][4] = {};
    #pragma unroll
    for (int c = 0; c < 32; c++) {
        float q[4], k[4];
        #pragma unroll
        for (int u = 0; u < 4; u++) { q[u] = Qs[ti*4+u][c]; k[u] = Ks[tj*4+u][c]; }
        #pragma unroll
        for (int i2 = 0; i2 < 4; i2++)
            #pragma unroll
            for (int j2 = 0; j2 < 4; j2++)
                acc[i2][j2] = fmaf(q[i2], k[j2], acc[i2][j2]);
    }
    #pragma unroll
    for (int i2 = 0; i2 < 4; i2++) {
        int i = ti*4 + i2;
        float4 v = make_float4(acc[i2][0]*INV_SCALE, acc[i2][1]*INV_SCALE,
                               acc[i2][2]*INV_SCALE, acc[i2][3]*INV_SCALE);
        *(float4*)(g_s + ((size_t)(bh*NN + i)*NN + l)*NN + tj*4) = v;
    }
}

// ---------------- softmax over l on s[b][h][i][l][j] (contiguous tile) ------------
__global__ __launch_bounds__(256)
void softmax_kernel() {
    int bid = blockIdx.x;            // bh*64 + i
    size_t base = (size_t)bid * 4096;
    int t = threadIdx.x;
    int j = t & 63, lq = t >> 6;     // 4 l-groups of 16
    __shared__ float pm[4][64], ps[4][64];
    float v[16];
    float mx = -1e30f;
    #pragma unroll
    for (int u = 0; u < 16; u++) {
        v[u] = g_s[base + (size_t)(lq*16 + u)*64 + j];
        mx = fmaxf(mx, v[u]);
    }
    pm[lq][j] = mx;
    __syncthreads();
    mx = fmaxf(fmaxf(pm[0][j], pm[1][j]), fmaxf(pm[2][j], pm[3][j]));
    float s = 0.f;
    #pragma unroll
    for (int u = 0; u < 16; u++) { v[u] = __expf(v[u] - mx); s += v[u]; }
    ps[lq][j] = s;
    __syncthreads();
    float inv = 1.f / (ps[0][j] + ps[1][j] + ps[2][j] + ps[3][j]);
    #pragma unroll
    for (int u = 0; u < 16; u++)
        g_s[base + (size_t)(lq*16 + u)*64 + j] = v[u] * inv;
}

// ---------------- tiled attn_o (round-8 structure; writes split bf16) ----------------
#define AT_V1 0                         // [i][l][36] floats
#define AT_V2 (16*16*36)                // [l][j][36]
#define AT_A  (2*16*16*36)              // [l][i][16]
#define ATTN_SMEM ((2*16*16*36 + 16*16*16)*4)

__global__ __launch_bounds__(256)
void attn_o_kernel() {
    extern __shared__ __align__(16) float sm[];
    float* v1s = sm + AT_V1;
    float* v2s = sm + AT_V2;
    float* as_ = sm + AT_A;
    int bx = blockIdx.x;
    int jt = bx & 3;
    int it = (bx >> 2) & 3;
    int h  = (bx >> 4) & 3;
    int b  = bx >> 6;
    int bh = b*HH + h;
    int i0 = it*16, j0 = jt*16;
    int t = threadIdx.x;
    int ti = t >> 4, tj = t & 15;

    float acc[32];
    #pragma unroll
    for (int d = 0; d < 32; d++) acc[d] = 0.f;

    for (int lc = 0; lc < 4; lc++) {
        int l0 = lc*16;
        #pragma unroll
        for (int k = 0; k < 8; k++) {
            int fid = t + k*256;
            int dq = fid & 7, l = (fid >> 3) & 15, i_ = fid >> 7;
            float4 v = *(const float4*)(g_qkv +
                ((size_t)((b*NN + i0 + i_)*NN + l0 + l))*512 + 256 + h*DHH + dq*4);
            *(float4*)(v1s + (i_*16 + l)*36 + dq*4) = v;
        }
        #pragma unroll
        for (int k = 0; k < 8; k++) {
            int fid = t + k*256;
            int dq = fid & 7, j_ = (fid >> 3) & 15, l_ = fid >> 7;
            float4 v = *(const float4*)(g_qkv +
                ((size_t)((b*NN + l0 + l_)*NN + j0 + j_))*512 + 384 + h*DHH + dq*4);
            *(float4*)(v2s + (l_*16 + j_)*36 + dq*4) = v;
        }
        #pragma unroll
        for (int k = 0; k < 4; k++) {
            int fid = t + k*256;
            int jq = fid & 3, i_ = (fid >> 2) & 15, l_ = fid >> 6;
            float4 v = *(const float4*)(g_s +
                ((size_t)(bh*NN + i0 + i_)*NN + l0 + l_)*NN + j0 + jq*4);
            *(float4*)(as_ + (l_*16 + i_)*16 + jq*4) = v;
        }
        __syncthreads();
        #pragma unroll 4
        for (int l = 0; l < 16; l++) {
            float a = as_[(l*16 + ti)*16 + tj];
            const float* p1 = v1s + (ti*16 + l)*36;
            const float* p2 = v2s + (l*16 + tj)*36;
            #pragma unroll
            for (int dq = 0; dq < 8; dq++) {
                float4 x = *(const float4*)(p1 + dq*4);
                float4 y = *(const float4*)(p2 + dq*4);
                acc[dq*4+0] = fmaf(a, x.x * y.x, acc[dq*4+0]);
                acc[dq*4+1] = fmaf(a, x.y * y.y, acc[dq*4+1]);
                acc[dq*4+2] = fmaf(a, x.z * y.z, acc[dq*4+2]);
                acc[dq*4+3] = fmaf(a, x.w * y.w, acc[dq*4+3]);
            }
        }
        __syncthreads();
    }
    size_t obase = ((size_t)((b*NN + i0 + ti)*NN + j0 + tj) << 7) + h*DHH;
    #pragma unroll
    for (int dq = 0; dq < 8; dq++) {
        __nv_bfloat16 h0,l0_,h1,l1,h2,l2,h3,l3;
        bsplit(acc[dq*4+0],h0,l0_); bsplit(acc[dq*4+1],h1,l1);
        bsplit(acc[dq*4+2],h2,l2);  bsplit(acc[dq*4+3],h3,l3);
        *(uint2*)(g_o_h + obase + dq*4) = make_uint2(pack2bf(h0,h1), pack2bf(h2,h3));
        *(uint2*)(g_o_l + obase + dq*4) = make_uint2(pack2bf(l0_,l1), pack2bf(l2,l3));
    }
}

// ---------------- final: out[b,n] = diag_tok . Wout + bout ----------------
__global__ __launch_bounds__(128)
void out_kernel(const float* __restrict__ Wout, const float* __restrict__ bout,
                float* __restrict__ out) {
    int bn = blockIdx.x;             // b*64 + n
    int n = bn & 63;
    int d = threadIdx.x;
    float v = g_tok[((size_t)bn*NN + n)*DD + d] * Wout[d];
    __shared__ float r[4];
    #pragma unroll
    for (int o = 16; o > 0; o >>= 1) v += __shfl_xor_sync(0xffffffffu, v, o);
    if ((d & 31) == 0) r[d >> 5] = v;
    __syncthreads();
    if (d == 0) out[bn] = r[0] + r[1] + r[2] + r[3] + bout[0];
}

// ---------------- host driver ----------------
extern "C" void kernel_launch(void* const* d_in, const int* in_sizes, int n_in,
                              void* d_out, int out_size) {
    const float* x    = (const float*)d_in[0];
    const float* ea   = (const float*)d_in[1];
    const void*  mask = d_in[2];
    const float* nW   = (const float*)d_in[3];
    const float* nb   = (const float*)d_in[4];
    const float* eW   = (const float*)d_in[5];
    const float* eb   = (const float*)d_in[6];
    const float* noe  = (const float*)d_in[7];
    const float* Wq   = (const float*)d_in[8];
    const float* Wk   = (const float*)d_in[9];
    const float* Wv1  = (const float*)d_in[10];
    const float* Wv2  = (const float*)d_in[11];
    const float* Wo   = (const float*)d_in[12];
    const float* bo   = (const float*)d_in[13];
    const float* ln1g = (const float*)d_in[14];
    const float* ln1b = (const float*)d_in[15];
    const float* W1   = (const float*)d_in[16];
    const float* b1   = (const float*)d_in[17];
    const float* W2   = (const float*)d_in[18];
    const float* b2   = (const float*)d_in[19];
    const float* ln2g = (const float*)d_in[20];
    const float* ln2b = (const float*)d_in[21];
    const float* Wout = (const float*)d_in[22];
    const float* bout = (const float*)d_in[23];

    float *tok, *qkv;
    __nv_bfloat16 *tokh, *tokl, *oh_, *ol_, *hidh, *hidl;
    __nv_bfloat16 *wqkvh, *wqkvl, *woh, *wol, *w1h, *w1l, *w2h, *w2l;
    cudaGetSymbolAddress((void**)&tok,   g_tok);
    cudaGetSymbolAddress((void**)&qkv,   g_qkv);
    cudaGetSymbolAddress((void**)&tokh,  g_tok_h);
    cudaGetSymbolAddress((void**)&tokl,  g_tok_l);
    cudaGetSymbolAddress((void**)&oh_,   g_o_h);
    cudaGetSymbolAddress((void**)&ol_,   g_o_l);
    cudaGetSymbolAddress((void**)&hidh,  g_hid_h);
    cudaGetSymbolAddress((void**)&hidl,  g_hid_l);
    cudaGetSymbolAddress((void**)&wqkvh, g_wqkvT_h);
    cudaGetSymbolAddress((void**)&wqkvl, g_wqkvT_l);
    cudaGetSymbolAddress((void**)&woh,   g_woT_h);
    cudaGetSymbolAddress((void**)&wol,   g_woT_l);
    cudaGetSymbolAddress((void**)&w1h,   g_w1T_h);
    cudaGetSymbolAddress((void**)&w1l,   g_w1T_l);
    cudaGetSymbolAddress((void**)&w2h,   g_w2T_h);
    cudaGetSymbolAddress((void**)&w2l,   g_w2T_l);

    cudaFuncSetAttribute(mma_gemm_kernel,
                         cudaFuncAttributeMaxDynamicSharedMemorySize, GSMEM);
    cudaFuncSetAttribute(attn_o_kernel,
                         cudaFuncAttributeMaxDynamicSharedMemorySize, ATTN_SMEM);

    detect_mask_kernel<<<1, 256>>>((const unsigned char*)mask);
    pack_all_kernel<<<2496, 256>>>(Wq, Wk, Wv1, Wv2, Wo, W1, W2,
                                   wqkvh, wqkvl, woh, wol, w1h, w1l, w2h, w2l);
    embed_kernel<<<MROWS, DD>>>(x, ea, mask, nW, nb, eW, eb, noe);

    dim3 gN128(1, MROWS/128);
    dim3 gN512(4, MROWS/128);

    for (int l = 0; l < LL; l++) {
        const __nv_bfloat16* wqh = wqkvh + (size_t)l*512*128;
        const __nv_bfloat16* wql = wqkvl + (size_t)l*512*128;
        const __nv_bfloat16* wo_h = woh + (size_t)l*128*128;
        const __nv_bfloat16* wo_l = wol + (size_t)l*128*128;
        const __nv_bfloat16* w1_h = w1h + (size_t)l*512*128;
        const __nv_bfloat16* w1_l = w1l + (size_t)l*512*128;
        const __nv_bfloat16* w2_h = w2h + (size_t)l*128*512;
        const __nv_bfloat16* w2_l = w2l + (size_t)l*128*512;
        const float* bo_l  = bo  + (size_t)l*DD;
        const float* g1_l  = ln1g + (size_t)l*DD;
        const float* b1l_l = ln1b + (size_t)l*DD;
        const float* bf1_l = b1  + (size_t)l*FF;
        const float* bf2_l = b2  + (size_t)l*DD;
        const float* g2_l  = ln2g + (size_t)l*DD;
        const float* b2l_l = ln2b + (size_t)l*DD;

        // fused QKV projection: A = tok (split), C = qkv fp32
        mma_gemm_kernel<<<gN512, 512, GSMEM>>>(tokh, tokl, wqh, wql,
            nullptr, nullptr, nullptr, nullptr, qkv, nullptr, nullptr, 128, 512, 0);

        score_kernel<<<BB*HH*NN, 256>>>();
        softmax_kernel<<<BB*HH*NN, 256>>>();
        attn_o_kernel<<<512, 256, ATTN_SMEM>>>();

        // o-projection + bias + residual(tok) + LN1 -> tok fp32 + split
        mma_gemm_kernel<<<gN128, 512, GSMEM>>>(oh_, ol_, wo_h, wo_l,
            bo_l, tok, g1_l, b1l_l, tok, tokh, tokl, 128, 128, 0);
        // FFN up + relu -> hid split only
        mma_gemm_kernel<<<gN512, 512, GSMEM>>>(tokh, tokl, w1_h, w1_l,
            bf1_l, nullptr, nullptr, nullptr, nullptr, hidh, hidl, 128, 512, 1);
        // FFN down + bias + residual(tok) + LN2 -> tok fp32 + split
        mma_gemm_kernel<<<gN128, 512, GSMEM>>>(hidh, hidl, w2_h, w2_l,
            bf2_l, tok, g2_l, b2l_l, tok, tokh, tokl, 512, 128, 0);
    }

    out_kernel<<<BB*NN, 128>>>(Wout, bout, (float*)d_out);
}

// round 12
// speedup vs baseline: 1.1262x; 1.0633x over previous
#include <cuda_runtime.h>
#include <cuda_bf16.h>
#include <math.h>
#include <stdint.h>

// ---------------- problem constants ----------------
#define BB 8
#define NN 64
#define IN_DIM 16
#define EDGE_DIM 8
#define DD 128
#define HH 4
#define DHH 32
#define LL 3
#define FF 512
#define MROWS (BB*NN*NN)          // 32768
static const float INV_SCALE = 0.17677669529663687f; // 1/sqrt(32)

// ---------------- scratch (device globals; no runtime alloc) ----------------
__device__ float g_tok  [(size_t)MROWS*DD];
__device__ float g_qkv  [(size_t)MROWS*512];          // q|k|v1|v2 packed along N
__device__ float g_s    [(size_t)BB*HH*NN*NN*NN];     // [b][h][i][l][j]
// bf16 hi/lo activation copies (GEMM A operands)
__device__ __nv_bfloat16 g_tok_h[(size_t)MROWS*DD];
__device__ __nv_bfloat16 g_tok_l[(size_t)MROWS*DD];
__device__ __nv_bfloat16 g_o_h  [(size_t)MROWS*DD];
__device__ __nv_bfloat16 g_o_l  [(size_t)MROWS*DD];
__device__ __nv_bfloat16 g_hid_h[(size_t)MROWS*FF];
__device__ __nv_bfloat16 g_hid_l[(size_t)MROWS*FF];
// transposed + bf16-split weights: layout [l][N][K]
__device__ __nv_bfloat16 g_wqkvT_h[(size_t)LL*512*128];
__device__ __nv_bfloat16 g_wqkvT_l[(size_t)LL*512*128];
__device__ __nv_bfloat16 g_woT_h  [(size_t)LL*128*128];
__device__ __nv_bfloat16 g_woT_l  [(size_t)LL*128*128];
__device__ __nv_bfloat16 g_w1T_h  [(size_t)LL*512*128];
__device__ __nv_bfloat16 g_w1T_l  [(size_t)LL*512*128];
__device__ __nv_bfloat16 g_w2T_h  [(size_t)LL*128*512];
__device__ __nv_bfloat16 g_w2T_l  [(size_t)LL*128*512];
__device__ int g_mask_mode;                            // 0=int32, 1=uint8, 2=float32

// ---------------- helpers ----------------
__device__ __forceinline__ void bsplit(float v, __nv_bfloat16& h, __nv_bfloat16& l) {
    h = __float2bfloat16(v);
    l = __float2bfloat16(v - __bfloat162float(h));
}
__device__ __forceinline__ uint32_t pack2bf(__nv_bfloat16 a, __nv_bfloat16 b) {
    return (uint32_t)__bfloat16_as_ushort(a) | ((uint32_t)__bfloat16_as_ushort(b) << 16);
}
__device__ __forceinline__ uint32_t smem_u32(const void* p) {
    uint32_t a;
    asm("{ .reg .u64 t; cvta.to.shared.u64 t, %1; cvt.u32.u64 %0, t; }" : "=r"(a) : "l"(p));
    return a;
}
// D += A*B  (m16n8k16, bf16 in, f32 acc)
__device__ __forceinline__ void mma16816(float* c, const uint32_t* a, const uint32_t* b) {
    asm volatile(
        "mma.sync.aligned.m16n8k16.row.col.f32.bf16.bf16.f32 "
        "{%0,%1,%2,%3}, {%4,%5,%6,%7}, {%8,%9}, {%0,%1,%2,%3};"
        : "+f"(c[0]), "+f"(c[1]), "+f"(c[2]), "+f"(c[3])
        : "r"(a[0]), "r"(a[1]), "r"(a[2]), "r"(a[3]), "r"(b[0]), "r"(b[1]));
}
__device__ __forceinline__ void ldsm4(uint32_t addr, uint32_t* r) {
    asm volatile("ldmatrix.sync.aligned.m8n8.x4.shared.b16 {%0,%1,%2,%3}, [%4];"
        : "=r"(r[0]), "=r"(r[1]), "=r"(r[2]), "=r"(r[3]) : "r"(addr));
}
__device__ __forceinline__ void cpa16(uint32_t saddr, const void* g) {
    asm volatile("cp.async.cg.shared.global [%0], [%1], 16;" :: "r"(saddr), "l"(g));
}

// ---------------- mask dtype detector ----------------
__global__ void detect_mask_kernel(const unsigned char* __restrict__ m) {
    __shared__ int has3f, hasodd;
    if (threadIdx.x == 0) { has3f = 0; hasodd = 0; }
    __syncthreads();
    for (int i = threadIdx.x; i < 4096; i += blockDim.x) {
        unsigned char v = m[i];
        if (v == 0x3F) atomicOr(&has3f, 1);
        if (v != 0 && (i & 3)) atomicOr(&hasodd, 1);
    }
    __syncthreads();
    if (threadIdx.x == 0) g_mask_mode = has3f ? 2 : (hasodd ? 1 : 0);
}

// ---------------- merged weight transpose + bf16 split ----------------
__global__ void pack_all_kernel(const float* __restrict__ Wq, const float* __restrict__ Wk,
                                const float* __restrict__ Wv1, const float* __restrict__ Wv2,
                                const float* __restrict__ Wo, const float* __restrict__ W1,
                                const float* __restrict__ W2,
                                __nv_bfloat16* __restrict__ qh, __nv_bfloat16* __restrict__ ql,
                                __nv_bfloat16* __restrict__ oh, __nv_bfloat16* __restrict__ ol,
                                __nv_bfloat16* __restrict__ h1, __nv_bfloat16* __restrict__ l1,
                                __nv_bfloat16* __restrict__ h2, __nv_bfloat16* __restrict__ l2) {
    int blk = blockIdx.x;
    const float* src; __nv_bfloat16 *dh, *dl;
    int K, N, dstN, nOff, idx;
    if (blk < 768) {
        int seg = blk / 192;
        idx = (blk - seg*192)*256 + threadIdx.x;
        src = (seg==0)?Wq:(seg==1)?Wk:(seg==2)?Wv1:Wv2;
        dh = qh; dl = ql; K = 128; N = 128; dstN = 512; nOff = seg*128;
    } else if (blk < 960) {
        idx = (blk-768)*256 + threadIdx.x;
        src = Wo; dh = oh; dl = ol; K = 128; N = 128; dstN = 128; nOff = 0;
    } else if (blk < 1728) {
        idx = (blk-960)*256 + threadIdx.x;
        src = W1; dh = h1; dl = l1; K = 128; N = 512; dstN = 512; nOff = 0;
    } else {
        idx = (blk-1728)*256 + threadIdx.x;
        src = W2; dh = h2; dl = l2; K = 512; N = 128; dstN = 128; nOff = 0;
    }
    if (idx >= LL*N*K) return;
    int k = idx % K;
    int n = (idx / K) % N;
    int ll = idx / (K*N);
    float v = src[((size_t)ll*K + k)*N + n];
    __nv_bfloat16 vh, vl; bsplit(v, vh, vl);
    size_t o = ((size_t)ll*dstN + nOff + n)*K + k;
    dh[o] = vh; dl[o] = vl;
}

// ---------------- embedding (fp32 + hi/lo) ----------------
__global__ void embed_kernel(const float* __restrict__ x,
                             const float* __restrict__ ea,
                             const void*  __restrict__ mask,
                             const float* __restrict__ nW, const float* __restrict__ nb,
                             const float* __restrict__ eW, const float* __restrict__ eb,
                             const float* __restrict__ noe) {
    int idx = blockIdx.x;                 // b*N*N + i*N + j
    int j = idx & 63;
    int i = (idx >> 6) & 63;
    int b = idx >> 12;
    int d = threadIdx.x;                  // 0..127
    __shared__ float sx[IN_DIM];
    __shared__ float se[EDGE_DIM];
    if (threadIdx.x < IN_DIM)  sx[threadIdx.x] = x[(b*NN + i)*IN_DIM + threadIdx.x];
    if (threadIdx.x < EDGE_DIM) se[threadIdx.x] = ea[((size_t)idx)*EDGE_DIM + threadIdx.x];
    __syncthreads();
    float v;
    if (i == j) {
        v = nb[d];
        #pragma unroll
        for (int e = 0; e < IN_DIM; e++) v = fmaf(sx[e], nW[e*DD + d], v);
    } else {
        bool m;
        int mm = g_mask_mode;
        if (mm == 0)      m = ((const int*)mask)[idx] != 0;
        else if (mm == 1) m = ((const unsigned char*)mask)[idx] != 0;
        else              m = ((const float*)mask)[idx] != 0.f;
        if (m) {
            v = eb[d];
            #pragma unroll
            for (int e = 0; e < EDGE_DIM; e++) v = fmaf(se[e], eW[e*DD + d], v);
        } else {
            v = noe[d];
        }
    }
    size_t off = (size_t)idx*DD + d;
    g_tok[off] = v;
    __nv_bfloat16 vh, vl; bsplit(v, vh, vl);
    g_tok_h[off] = vh; g_tok_l[off] = vl;
}

// ================= cp.async double-buffered mma.sync bf16 GEMM =================
// CTA tile 64x128, 256 threads, warp grid 2x4, warp tile 32x32, K chunk 64,
// 2-stage cp.async pipeline. 96KB smem -> 2 CTAs/SM.
// smem tiles (per stage): Ah 8KB | Al 8KB | Bh 16KB | Bl 16KB
// XOR swizzle: byte = row*128 + ((c16 ^ (row&7))<<4)
#define AT_B  8192
#define BT_B  16384
#define STAGE_B (2*AT_B + 2*BT_B)     // 49152
#define OFF_AL  AT_B
#define OFF_BH  (2*AT_B)
#define OFF_BL  (2*AT_B + BT_B)
#define GSMEM (2*STAGE_B)             // 98304 bytes

__global__ __launch_bounds__(256, 2)
void mma_gemm_kernel(const __nv_bfloat16* __restrict__ Agh,
                     const __nv_bfloat16* __restrict__ Agl,
                     const __nv_bfloat16* __restrict__ Bgh,
                     const __nv_bfloat16* __restrict__ Bgl,
                     const float* __restrict__ bias, const float* __restrict__ res,
                     const float* __restrict__ lng, const float* __restrict__ lnb,
                     float* __restrict__ Cf,
                     __nv_bfloat16* __restrict__ Ch, __nv_bfloat16* __restrict__ Cl,
                     int Kt, int Nt, int relu) {
    extern __shared__ __align__(16) char smem[];
    uint32_t smb = smem_u32(smem);
    int t   = threadIdx.x;
    int wid = t >> 5, lid = t & 31;
    int g   = lid >> 2, tg = lid & 3;
    int wm0 = (wid >> 2) * 32;           // 2 warp-rows (0,32)
    int wn0 = (wid & 3) * 32;            // 4 warp-cols
    int bn  = blockIdx.x << 7;
    int bm  = blockIdx.y << 6;           // BM = 64

    float acc[2][4][4];
    #pragma unroll
    for (int mt = 0; mt < 2; mt++)
        #pragma unroll
        for (int nt = 0; nt < 4; nt++)
            #pragma unroll
            for (int rr = 0; rr < 4; rr++) acc[mt][nt][rr] = 0.f;

    int nch = Kt >> 6;

    auto load_chunk = [&](int ch, int stg) {
        int k0 = ch << 6;
        uint32_t sb = smb + stg*STAGE_B;
        // A tiles: 64 rows, 512 segs each (2 per thread)
        #pragma unroll
        for (int p = 0; p < 2; p++) {
            int seg = t + p*256;
            int row = seg >> 3, c16 = seg & 7;
            uint32_t sw = (uint32_t)(row*128) + (((uint32_t)(c16 ^ (row & 7))) << 4);
            const __nv_bfloat16* gh = Agh + (size_t)(bm + row)*Kt + k0 + c16*8;
            const __nv_bfloat16* gl = Agl + (size_t)(bm + row)*Kt + k0 + c16*8;
            cpa16(sb + sw, gh);
            cpa16(sb + OFF_AL + sw, gl);
        }
        // B tiles: 128 rows, 1024 segs each (4 per thread)
        #pragma unroll
        for (int p = 0; p < 4; p++) {
            int seg = t + p*256;
            int row = seg >> 3, c16 = seg & 7;
            uint32_t sw = (uint32_t)(row*128) + (((uint32_t)(c16 ^ (row & 7))) << 4);
            const __nv_bfloat16* gh = Bgh + (size_t)(bn + row)*Kt + k0 + c16*8;
            const __nv_bfloat16* gl = Bgl + (size_t)(bn + row)*Kt + k0 + c16*8;
            cpa16(sb + OFF_BH + sw, gh);
            cpa16(sb + OFF_BL + sw, gl);
        }
        asm volatile("cp.async.commit_group;" ::: "memory");
    };

    load_chunk(0, 0);
    for (int ch = 0; ch < nch; ch++) {
        if (ch + 1 < nch) {
            load_chunk(ch + 1, (ch + 1) & 1);
            asm volatile("cp.async.wait_group 1;" ::: "memory");
        } else {
            asm volatile("cp.async.wait_group 0;" ::: "memory");
        }
        __syncthreads();
        uint32_t sb = smb + (ch & 1)*STAGE_B;
        #pragma unroll
        for (int ks = 0; ks < 4; ks++) {
            uint32_t ah[2][4], al[2][4];
            int ac16 = ks*2 + (lid >> 4);
            #pragma unroll
            for (int mt = 0; mt < 2; mt++) {
                int row = wm0 + mt*16 + (lid & 15);
                uint32_t off = (uint32_t)(row*128) + (((uint32_t)(ac16 ^ (row & 7))) << 4);
                ldsm4(sb + off, ah[mt]);
                ldsm4(sb + OFF_AL + off, al[mt]);
            }
            int bc16 = ks*2 + ((lid >> 3) & 1);
            #pragma unroll
            for (int np = 0; np < 2; np++) {
                int row = wn0 + np*16 + ((lid >> 4) & 1)*8 + (lid & 7);
                uint32_t off = (uint32_t)(row*128) + (((uint32_t)(bc16 ^ (row & 7))) << 4);
                uint32_t bh4[4], bl4[4];
                ldsm4(sb + OFF_BH + off, bh4);
                ldsm4(sb + OFF_BL + off, bl4);
                #pragma unroll
                for (int half = 0; half < 2; half++) {
                    int nt = np*2 + half;
                    #pragma unroll
                    for (int mt = 0; mt < 2; mt++) {
                        mma16816(acc[mt][nt], ah[mt], bh4 + half*2);
                        mma16816(acc[mt][nt], ah[mt], bl4 + half*2);
                        mma16816(acc[mt][nt], al[mt], bh4 + half*2);
                    }
                }
            }
        }
        __syncthreads();
    }

    // ---------------- epilogue: bias / residual / relu ----------------
    #pragma unroll
    for (int nt = 0; nt < 4; nt++) {
        int colg = bn + wn0 + nt*8 + tg*2;
        float b0 = 0.f, b1 = 0.f;
        if (bias) { b0 = bias[colg]; b1 = bias[colg+1]; }
        #pragma unroll
        for (int mt = 0; mt < 2; mt++) {
            #pragma unroll
            for (int rp = 0; rp < 2; rp++) {
                int rowg = bm + wm0 + mt*16 + rp*8 + g;
                float v0 = acc[mt][nt][rp*2]   + b0;
                float v1 = acc[mt][nt][rp*2+1] + b1;
                if (res) {
                    float2 rv = *(const float2*)(res + (size_t)rowg*Nt + colg);
                    v0 += rv.x; v1 += rv.y;
                }
                if (relu) { v0 = fmaxf(v0, 0.f); v1 = fmaxf(v1, 0.f); }
                acc[mt][nt][rp*2]   = v0;
                acc[mt][nt][rp*2+1] = v1;
            }
        }
    }

    if (lng) {
        // LN over last dim; only used with Nt==128 (4 col-warps per row, 64 rows).
        float* rs = (float*)smem;        // [64][4]
        float* rq = rs + 256;            // [64][4]
        #pragma unroll
        for (int mt = 0; mt < 2; mt++) {
            #pragma unroll
            for (int rp = 0; rp < 2; rp++) {
                float s = 0.f, q = 0.f;
                #pragma unroll
                for (int nt = 0; nt < 4; nt++) {
                    float v0 = acc[mt][nt][rp*2], v1 = acc[mt][nt][rp*2+1];
                    s += v0 + v1;
                    q += v0*v0 + v1*v1;
                }
                s += __shfl_xor_sync(0xffffffffu, s, 1);
                s += __shfl_xor_sync(0xffffffffu, s, 2);
                q += __shfl_xor_sync(0xffffffffu, q, 1);
                q += __shfl_xor_sync(0xffffffffu, q, 2);
                if (tg == 0) {
                    int row = wm0 + mt*16 + rp*8 + g;
                    rs[row*4 + (wid & 3)] = s;
                    rq[row*4 + (wid & 3)] = q;
                }
            }
        }
        __syncthreads();
        #pragma unroll
        for (int mt = 0; mt < 2; mt++) {
            #pragma unroll
            for (int rp = 0; rp < 2; rp++) {
                int row = wm0 + mt*16 + rp*8 + g;
                float s = rs[row*4] + rs[row*4+1] + rs[row*4+2] + rs[row*4+3];
                float q = rq[row*4] + rq[row*4+1] + rq[row*4+2] + rq[row*4+3];
                float mean = s * 0.0078125f;
                float rstd = rsqrtf(q * 0.0078125f - mean*mean + 1e-5f);
                size_t rowoff = (size_t)(bm + row)*Nt;
                #pragma unroll
                for (int nt = 0; nt < 4; nt++) {
                    int col = wn0 + nt*8 + tg*2;
                    float2 gg = *(const float2*)(lng + col);
                    float2 gb = *(const float2*)(lnb + col);
                    float v0 = (acc[mt][nt][rp*2]   - mean)*rstd*gg.x + gb.x;
                    float v1 = (acc[mt][nt][rp*2+1] - mean)*rstd*gg.y + gb.y;
                    *(float2*)(Cf + rowoff + bn + col) = make_float2(v0, v1);
                    __nv_bfloat16 h0,l0,h1,l1;
                    bsplit(v0,h0,l0); bsplit(v1,h1,l1);
                    *(uint32_t*)(Ch + rowoff + bn + col) = pack2bf(h0,h1);
                    *(uint32_t*)(Cl + rowoff + bn + col) = pack2bf(l0,l1);
                }
            }
        }
    } else {
        #pragma unroll
        for (int mt = 0; mt < 2; mt++) {
            #pragma unroll
            for (int rp = 0; rp < 2; rp++) {
                int rowg = bm + wm0 + mt*16 + rp*8 + g;
                size_t rowoff = (size_t)rowg*Nt;
                #pragma unroll
                for (int nt = 0; nt < 4; nt++) {
                    int colg = bn + wn0 + nt*8 + tg*2;
                    float v0 = acc[mt][nt][rp*2], v1 = acc[mt][nt][rp*2+1];
                    if (Cf) *(float2*)(Cf + rowoff + colg) = make_float2(v0, v1);
                    if (Ch) {
                        __nv_bfloat16 h0,l0,h1,l1;
                        bsplit(v0,h0,l0); bsplit(v1,h1,l1);
                        *(uint32_t*)(Ch + rowoff + colg) = pack2bf(h0,h1);
                        *(uint32_t*)(Cl + rowoff + colg) = pack2bf(l0,l1);
                    }
                }
            }
        }
    }
}

// ---------------- scores: s[b,h,i,l,j] = (1/SCALE) * q[b,i,l,h,:] . k[b,l,j,h,:] ------
__global__ __launch_bounds__(256)
void score_kernel() {
    int bid = blockIdx.x;                  // bh*64 + l
    int l  = bid & 63;
    int bh = bid >> 6;
    int h  = bh & 3;
    int b  = bh >> 2;
    __shared__ float Qs[64][33];
    __shared__ float Ks[64][33];
    int t = threadIdx.x;
    for (int idx = t; idx < 64*32; idx += 256) {
        int r = idx >> 5, c = idx & 31;
        Qs[r][c] = g_qkv[((size_t)((b*NN + r)*NN + l))*512 +       h*DHH + c]; // q, r=i
        Ks[r][c] = g_qkv[((size_t)((b*NN + l)*NN + r))*512 + 128 + h*DHH + c]; // k, r=j
    }
    __syncthreads();
    int tj = t & 15, ti = t >> 4;
    float acc[4][4] = {};
    #pragma unroll
    for (int c = 0; c < 32; c++) {
        float q[4], k[4];
        #pragma unroll
        for (int u = 0; u < 4; u++) { q[u] = Qs[ti*4+u][c]; k[u] = Ks[tj*4+u][c]; }
        #pragma unroll
        for (int i2 = 0; i2 < 4; i2++)
            #pragma unroll
            for (int j2 = 0; j2 < 4; j2++)
                acc[i2][j2] = fmaf(q[i2], k[j2], acc[i2][j2]);
    }
    #pragma unroll
    for (int i2 = 0; i2 < 4; i2++) {
        int i = ti*4 + i2;
        float4 v = make_float4(acc[i2][0]*INV_SCALE, acc[i2][1]*INV_SCALE,
                               acc[i2][2]*INV_SCALE, acc[i2][3]*INV_SCALE);
        *(float4*)(g_s + ((size_t)(bh*NN + i)*NN + l)*NN + tj*4) = v;
    }
}

// ---------------- softmax over l on s[b][h][i][l][j] (contiguous tile) ------------
__global__ __launch_bounds__(256)
void softmax_kernel() {
    int bid = blockIdx.x;            // bh*64 + i
    size_t base = (size_t)bid * 4096;
    int t = threadIdx.x;
    int j = t & 63, lq = t >> 6;     // 4 l-groups of 16
    __shared__ float pm[4][64], ps[4][64];
    float v[16];
    float mx = -1e30f;
    #pragma unroll
    for (int u = 0; u < 16; u++) {
        v[u] = g_s[base + (size_t)(lq*16 + u)*64 + j];
        mx = fmaxf(mx, v[u]);
    }
    pm[lq][j] = mx;
    __syncthreads();
    mx = fmaxf(fmaxf(pm[0][j], pm[1][j]), fmaxf(pm[2][j], pm[3][j]));
    float s = 0.f;
    #pragma unroll
    for (int u = 0; u < 16; u++) { v[u] = __expf(v[u] - mx); s += v[u]; }
    ps[lq][j] = s;
    __syncthreads();
    float inv = 1.f / (ps[0][j] + ps[1][j] + ps[2][j] + ps[3][j]);
    #pragma unroll
    for (int u = 0; u < 16; u++)
        g_s[base + (size_t)(lq*16 + u)*64 + j] = v[u] * inv;
}

// ---------------- tiled attn_o (round-8 structure; writes split bf16) ----------------
#define AT_V1 0                         // [i][l][36] floats
#define AT_V2 (16*16*36)                // [l][j][36]
#define AT_A  (2*16*16*36)              // [l][i][16]
#define ATTN_SMEM ((2*16*16*36 + 16*16*16)*4)

__global__ __launch_bounds__(256)
void attn_o_kernel() {
    extern __shared__ __align__(16) float sm[];
    float* v1s = sm + AT_V1;
    float* v2s = sm + AT_V2;
    float* as_ = sm + AT_A;
    int bx = blockIdx.x;
    int jt = bx & 3;
    int it = (bx >> 2) & 3;
    int h  = (bx >> 4) & 3;
    int b  = bx >> 6;
    int bh = b*HH + h;
    int i0 = it*16, j0 = jt*16;
    int t = threadIdx.x;
    int ti = t >> 4, tj = t & 15;

    float acc[32];
    #pragma unroll
    for (int d = 0; d < 32; d++) acc[d] = 0.f;

    for (int lc = 0; lc < 4; lc++) {
        int l0 = lc*16;
        #pragma unroll
        for (int k = 0; k < 8; k++) {
            int fid = t + k*256;
            int dq = fid & 7, l = (fid >> 3) & 15, i_ = fid >> 7;
            float4 v = *(const float4*)(g_qkv +
                ((size_t)((b*NN + i0 + i_)*NN + l0 + l))*512 + 256 + h*DHH + dq*4);
            *(float4*)(v1s + (i_*16 + l)*36 + dq*4) = v;
        }
        #pragma unroll
        for (int k = 0; k < 8; k++) {
            int fid = t + k*256;
            int dq = fid & 7, j_ = (fid >> 3) & 15, l_ = fid >> 7;
            float4 v = *(const float4*)(g_qkv +
                ((size_t)((b*NN + l0 + l_)*NN + j0 + j_))*512 + 384 + h*DHH + dq*4);
            *(float4*)(v2s + (l_*16 + j_)*36 + dq*4) = v;
        }
        #pragma unroll
        for (int k = 0; k < 4; k++) {
            int fid = t + k*256;
            int jq = fid & 3, i_ = (fid >> 2) & 15, l_ = fid >> 6;
            float4 v = *(const float4*)(g_s +
                ((size_t)(bh*NN + i0 + i_)*NN + l0 + l_)*NN + j0 + jq*4);
            *(float4*)(as_ + (l_*16 + i_)*16 + jq*4) = v;
        }
        __syncthreads();
        #pragma unroll 4
        for (int l = 0; l < 16; l++) {
            float a = as_[(l*16 + ti)*16 + tj];
            const float* p1 = v1s + (ti*16 + l)*36;
            const float* p2 = v2s + (l*16 + tj)*36;
            #pragma unroll
            for (int dq = 0; dq < 8; dq++) {
                float4 x = *(const float4*)(p1 + dq*4);
                float4 y = *(const float4*)(p2 + dq*4);
                acc[dq*4+0] = fmaf(a, x.x * y.x, acc[dq*4+0]);
                acc[dq*4+1] = fmaf(a, x.y * y.y, acc[dq*4+1]);
                acc[dq*4+2] = fmaf(a, x.z * y.z, acc[dq*4+2]);
                acc[dq*4+3] = fmaf(a, x.w * y.w, acc[dq*4+3]);
            }
        }
        __syncthreads();
    }
    size_t obase = ((size_t)((b*NN + i0 + ti)*NN + j0 + tj) << 7) + h*DHH;
    #pragma unroll
    for (int dq = 0; dq < 8; dq++) {
        __nv_bfloat16 h0,l0_,h1,l1,h2,l2,h3,l3;
        bsplit(acc[dq*4+0],h0,l0_); bsplit(acc[dq*4+1],h1,l1);
        bsplit(acc[dq*4+2],h2,l2);  bsplit(acc[dq*4+3],h3,l3);
        *(uint2*)(g_o_h + obase + dq*4) = make_uint2(pack2bf(h0,h1), pack2bf(h2,h3));
        *(uint2*)(g_o_l + obase + dq*4) = make_uint2(pack2bf(l0_,l1), pack2bf(l2,l3));
    }
}

// ---------------- final: out[b,n] = diag_tok . Wout + bout ----------------
__global__ __launch_bounds__(128)
void out_kernel(const float* __restrict__ Wout, const float* __restrict__ bout,
                float* __restrict__ out) {
    int bn = blockIdx.x;             // b*64 + n
    int n = bn & 63;
    int d = threadIdx.x;
    float v = g_tok[((size_t)bn*NN + n)*DD + d] * Wout[d];
    __shared__ float r[4];
    #pragma unroll
    for (int o = 16; o > 0; o >>= 1) v += __shfl_xor_sync(0xffffffffu, v, o);
    if ((d & 31) == 0) r[d >> 5] = v;
    __syncthreads();
    if (d == 0) out[bn] = r[0] + r[1] + r[2] + r[3] + bout[0];
}

// ---------------- host driver ----------------
extern "C" void kernel_launch(void* const* d_in, const int* in_sizes, int n_in,
                              void* d_out, int out_size) {
    const float* x    = (const float*)d_in[0];
    const float* ea   = (const float*)d_in[1];
    const void*  mask = d_in[2];
    const float* nW   = (const float*)d_in[3];
    const float* nb   = (const float*)d_in[4];
    const float* eW   = (const float*)d_in[5];
    const float* eb   = (const float*)d_in[6];
    const float* noe  = (const float*)d_in[7];
    const float* Wq   = (const float*)d_in[8];
    const float* Wk   = (const float*)d_in[9];
    const float* Wv1  = (const float*)d_in[10];
    const float* Wv2  = (const float*)d_in[11];
    const float* Wo   = (const float*)d_in[12];
    const float* bo   = (const float*)d_in[13];
    const float* ln1g = (const float*)d_in[14];
    const float* ln1b = (const float*)d_in[15];
    const float* W1   = (const float*)d_in[16];
    const float* b1   = (const float*)d_in[17];
    const float* W2   = (const float*)d_in[18];
    const float* b2   = (const float*)d_in[19];
    const float* ln2g = (const float*)d_in[20];
    const float* ln2b = (const float*)d_in[21];
    const float* Wout = (const float*)d_in[22];
    const float* bout = (const float*)d_in[23];

    float *tok, *qkv;
    __nv_bfloat16 *tokh, *tokl, *oh_, *ol_, *hidh, *hidl;
    __nv_bfloat16 *wqkvh, *wqkvl, *woh, *wol, *w1h, *w1l, *w2h, *w2l;
    cudaGetSymbolAddress((void**)&tok,   g_tok);
    cudaGetSymbolAddress((void**)&qkv,   g_qkv);
    cudaGetSymbolAddress((void**)&tokh,  g_tok_h);
    cudaGetSymbolAddress((void**)&tokl,  g_tok_l);
    cudaGetSymbolAddress((void**)&oh_,   g_o_h);
    cudaGetSymbolAddress((void**)&ol_,   g_o_l);
    cudaGetSymbolAddress((void**)&hidh,  g_hid_h);
    cudaGetSymbolAddress((void**)&hidl,  g_hid_l);
    cudaGetSymbolAddress((void**)&wqkvh, g_wqkvT_h);
    cudaGetSymbolAddress((void**)&wqkvl, g_wqkvT_l);
    cudaGetSymbolAddress((void**)&woh,   g_woT_h);
    cudaGetSymbolAddress((void**)&wol,   g_woT_l);
    cudaGetSymbolAddress((void**)&w1h,   g_w1T_h);
    cudaGetSymbolAddress((void**)&w1l,   g_w1T_l);
    cudaGetSymbolAddress((void**)&w2h,   g_w2T_h);
    cudaGetSymbolAddress((void**)&w2l,   g_w2T_l);

    cudaFuncSetAttribute(mma_gemm_kernel,
                         cudaFuncAttributeMaxDynamicSharedMemorySize, GSMEM);
    cudaFuncSetAttribute(attn_o_kernel,
                         cudaFuncAttributeMaxDynamicSharedMemorySize, ATTN_SMEM);

    detect_mask_kernel<<<1, 256>>>((const unsigned char*)mask);
    pack_all_kernel<<<2496, 256>>>(Wq, Wk, Wv1, Wv2, Wo, W1, W2,
                                   wqkvh, wqkvl, woh, wol, w1h, w1l, w2h, w2l);
    embed_kernel<<<MROWS, DD>>>(x, ea, mask, nW, nb, eW, eb, noe);

    dim3 gN128(1, MROWS/64);          // 512 blocks
    dim3 gN512(4, MROWS/64);          // 2048 blocks

    for (int l = 0; l < LL; l++) {
        const __nv_bfloat16* wqh = wqkvh + (size_t)l*512*128;
        const __nv_bfloat16* wql = wqkvl + (size_t)l*512*128;
        const __nv_bfloat16* wo_h = woh + (size_t)l*128*128;
        const __nv_bfloat16* wo_l = wol + (size_t)l*128*128;
        const __nv_bfloat16* w1_h = w1h + (size_t)l*512*128;
        const __nv_bfloat16* w1_l = w1l + (size_t)l*512*128;
        const __nv_bfloat16* w2_h = w2h + (size_t)l*128*512;
        const __nv_bfloat16* w2_l = w2l + (size_t)l*128*512;
        const float* bo_l  = bo  + (size_t)l*DD;
        const float* g1_l  = ln1g + (size_t)l*DD;
        const float* b1l_l = ln1b + (size_t)l*DD;
        const float* bf1_l = b1  + (size_t)l*FF;
        const float* bf2_l = b2  + (size_t)l*DD;
        const float* g2_l  = ln2g + (size_t)l*DD;
        const float* b2l_l = ln2b + (size_t)l*DD;

        // fused QKV projection: A = tok (split), C = qkv fp32
        mma_gemm_kernel<<<gN512, 256, GSMEM>>>(tokh, tokl, wqh, wql,
            nullptr, nullptr, nullptr, nullptr, qkv, nullptr, nullptr, 128, 512, 0);

        score_kernel<<<BB*HH*NN, 256>>>();
        softmax_kernel<<<BB*HH*NN, 256>>>();
        attn_o_kernel<<<512, 256, ATTN_SMEM>>>();

        // o-projection + bias + residual(tok) + LN1 -> tok fp32 + split
        mma_gemm_kernel<<<gN128, 256, GSMEM>>>(oh_, ol_, wo_h, wo_l,
            bo_l, tok, g1_l, b1l_l, tok, tokh, tokl, 128, 128, 0);
        // FFN up + relu -> hid split only
        mma_gemm_kernel<<<gN512, 256, GSMEM>>>(tokh, tokl, w1_h, w1_l,
            bf1_l, nullptr, nullptr, nullptr, nullptr, hidh, hidl, 128, 512, 1);
        // FFN down + bias + residual(tok) + LN2 -> tok fp32 + split
        mma_gemm_kernel<<<gN128, 256, GSMEM>>>(hidh, hidl, w2_h, w2_l,
            bf2_l, tok, g2_l, b2l_l, tok, tokh, tokl, 512, 128, 0);
    }

    out_kernel<<<BB*NN, 128>>>(Wout, bout, (float*)d_out);
}

// round 14
// speedup vs baseline: 1.1305x; 1.0038x over previous
#include <cuda_runtime.h>
#include <cuda_bf16.h>
#include <math.h>
#include <stdint.h>

// ---------------- problem constants ----------------
#define BB 8
#define NN 64
#define IN_DIM 16
#define EDGE_DIM 8
#define DD 128
#define HH 4
#define DHH 32
#define LL 3
#define FF 512
#define MROWS (BB*NN*NN)          // 32768
static const float INV_SCALE = 0.17677669529663687f; // 1/sqrt(32)

// ---------------- scratch (device globals; no runtime alloc) ----------------
__device__ float g_tok  [(size_t)MROWS*DD];
__device__ float g_qkv  [(size_t)MROWS*512];          // q|k|v1|v2 packed along N
__device__ float g_s    [(size_t)BB*HH*NN*NN*NN];     // [b][h][i][l][j]
// bf16 hi/lo activation copies (GEMM A operands)
__device__ __nv_bfloat16 g_tok_h[(size_t)MROWS*DD];
__device__ __nv_bfloat16 g_tok_l[(size_t)MROWS*DD];
__device__ __nv_bfloat16 g_o_h  [(size_t)MROWS*DD];
__device__ __nv_bfloat16 g_o_l  [(size_t)MROWS*DD];
__device__ __nv_bfloat16 g_hid_h[(size_t)MROWS*FF];
__device__ __nv_bfloat16 g_hid_l[(size_t)MROWS*FF];
// q|k split copies (cols 0..255 of qkv), stride 256
__device__ __nv_bfloat16 g_qk_h [(size_t)MROWS*256];
__device__ __nv_bfloat16 g_qk_l [(size_t)MROWS*256];
// transposed + bf16-split weights: layout [l][N][K]
__device__ __nv_bfloat16 g_wqkvT_h[(size_t)LL*512*128];
__device__ __nv_bfloat16 g_wqkvT_l[(size_t)LL*512*128];
__device__ __nv_bfloat16 g_woT_h  [(size_t)LL*128*128];
__device__ __nv_bfloat16 g_woT_l  [(size_t)LL*128*128];
__device__ __nv_bfloat16 g_w1T_h  [(size_t)LL*512*128];
__device__ __nv_bfloat16 g_w1T_l  [(size_t)LL*512*128];
__device__ __nv_bfloat16 g_w2T_h  [(size_t)LL*128*512];
__device__ __nv_bfloat16 g_w2T_l  [(size_t)LL*128*512];
__device__ int g_mask_mode;                            // 0=int32, 1=uint8, 2=float32

// ---------------- helpers ----------------
__device__ __forceinline__ void bsplit(float v, __nv_bfloat16& h, __nv_bfloat16& l) {
    h = __float2bfloat16(v);
    l = __float2bfloat16(v - __bfloat162float(h));
}
__device__ __forceinline__ uint32_t pack2bf(__nv_bfloat16 a, __nv_bfloat16 b) {
    return (uint32_t)__bfloat16_as_ushort(a) | ((uint32_t)__bfloat16_as_ushort(b) << 16);
}
__device__ __forceinline__ uint32_t smem_u32(const void* p) {
    uint32_t a;
    asm("{ .reg .u64 t; cvta.to.shared.u64 t, %1; cvt.u32.u64 %0, t; }" : "=r"(a) : "l"(p));
    return a;
}
// D += A*B  (m16n8k16, bf16 in, f32 acc)
__device__ __forceinline__ void mma16816(float* c, const uint32_t* a, const uint32_t* b) {
    asm volatile(
        "mma.sync.aligned.m16n8k16.row.col.f32.bf16.bf16.f32 "
        "{%0,%1,%2,%3}, {%4,%5,%6,%7}, {%8,%9}, {%0,%1,%2,%3};"
        : "+f"(c[0]), "+f"(c[1]), "+f"(c[2]), "+f"(c[3])
        : "r"(a[0]), "r"(a[1]), "r"(a[2]), "r"(a[3]), "r"(b[0]), "r"(b[1]));
}
__device__ __forceinline__ void ldsm4(uint32_t addr, uint32_t* r) {
    asm volatile("ldmatrix.sync.aligned.m8n8.x4.shared.b16 {%0,%1,%2,%3}, [%4];"
        : "=r"(r[0]), "=r"(r[1]), "=r"(r[2]), "=r"(r[3]) : "r"(addr));
}
__device__ __forceinline__ void cpa16(uint32_t saddr, const void* g) {
    asm volatile("cp.async.cg.shared.global [%0], [%1], 16;" :: "r"(saddr), "l"(g));
}

// ---------------- mask dtype detector ----------------
__global__ void detect_mask_kernel(const unsigned char* __restrict__ m) {
    __shared__ int has3f, hasodd;
    if (threadIdx.x == 0) { has3f = 0; hasodd = 0; }
    __syncthreads();
    for (int i = threadIdx.x; i < 4096; i += blockDim.x) {
        unsigned char v = m[i];
        if (v == 0x3F) atomicOr(&has3f, 1);
        if (v != 0 && (i & 3)) atomicOr(&hasodd, 1);
    }
    __syncthreads();
    if (threadIdx.x == 0) g_mask_mode = has3f ? 2 : (hasodd ? 1 : 0);
}

// ---------------- merged weight transpose + bf16 split ----------------
__global__ void pack_all_kernel(const float* __restrict__ Wq, const float* __restrict__ Wk,
                                const float* __restrict__ Wv1, const float* __restrict__ Wv2,
                                const float* __restrict__ Wo, const float* __restrict__ W1,
                                const float* __restrict__ W2,
                                __nv_bfloat16* __restrict__ qh, __nv_bfloat16* __restrict__ ql,
                                __nv_bfloat16* __restrict__ oh, __nv_bfloat16* __restrict__ ol,
                                __nv_bfloat16* __restrict__ h1, __nv_bfloat16* __restrict__ l1,
                                __nv_bfloat16* __restrict__ h2, __nv_bfloat16* __restrict__ l2) {
    int blk = blockIdx.x;
    const float* src; __nv_bfloat16 *dh, *dl;
    int K, N, dstN, nOff, idx;
    if (blk < 768) {
        int seg = blk / 192;
        idx = (blk - seg*192)*256 + threadIdx.x;
        src = (seg==0)?Wq:(seg==1)?Wk:(seg==2)?Wv1:Wv2;
        dh = qh; dl = ql; K = 128; N = 128; dstN = 512; nOff = seg*128;
    } else if (blk < 960) {
        idx = (blk-768)*256 + threadIdx.x;
        src = Wo; dh = oh; dl = ol; K = 128; N = 128; dstN = 128; nOff = 0;
    } else if (blk < 1728) {
        idx = (blk-960)*256 + threadIdx.x;
        src = W1; dh = h1; dl = l1; K = 128; N = 512; dstN = 512; nOff = 0;
    } else {
        idx = (blk-1728)*256 + threadIdx.x;
        src = W2; dh = h2; dl = l2; K = 512; N = 128; dstN = 128; nOff = 0;
    }
    if (idx >= LL*N*K) return;
    int k = idx % K;
    int n = (idx / K) % N;
    int ll = idx / (K*N);
    float v = src[((size_t)ll*K + k)*N + n];
    __nv_bfloat16 vh, vl; bsplit(v, vh, vl);
    size_t o = ((size_t)ll*dstN + nOff + n)*K + k;
    dh[o] = vh; dl[o] = vl;
}

// ---------------- embedding (fp32 + hi/lo) ----------------
__global__ void embed_kernel(const float* __restrict__ x,
                             const float* __restrict__ ea,
                             const void*  __restrict__ mask,
                             const float* __restrict__ nW, const float* __restrict__ nb,
                             const float* __restrict__ eW, const float* __restrict__ eb,
                             const float* __restrict__ noe) {
    int idx = blockIdx.x;                 // b*N*N + i*N + j
    int j = idx & 63;
    int i = (idx >> 6) & 63;
    int b = idx >> 12;
    int d = threadIdx.x;                  // 0..127
    __shared__ float sx[IN_DIM];
    __shared__ float se[EDGE_DIM];
    if (threadIdx.x < IN_DIM)  sx[threadIdx.x] = x[(b*NN + i)*IN_DIM + threadIdx.x];
    if (threadIdx.x < EDGE_DIM) se[threadIdx.x] = ea[((size_t)idx)*EDGE_DIM + threadIdx.x];
    __syncthreads();
    float v;
    if (i == j) {
        v = nb[d];
        #pragma unroll
        for (int e = 0; e < IN_DIM; e++) v = fmaf(sx[e], nW[e*DD + d], v);
    } else {
        bool m;
        int mm = g_mask_mode;
        if (mm == 0)      m = ((const int*)mask)[idx] != 0;
        else if (mm == 1) m = ((const unsigned char*)mask)[idx] != 0;
        else              m = ((const float*)mask)[idx] != 0.f;
        if (m) {
            v = eb[d];
            #pragma unroll
            for (int e = 0; e < EDGE_DIM; e++) v = fmaf(se[e], eW[e*DD + d], v);
        } else {
            v = noe[d];
        }
    }
    size_t off = (size_t)idx*DD + d;
    g_tok[off] = v;
    __nv_bfloat16 vh, vl; bsplit(v, vh, vl);
    g_tok_h[off] = vh; g_tok_l[off] = vl;
}

// ================= cp.async double-buffered mma.sync bf16 GEMM =================
// CTA tile 64x128, 256 threads, warp grid 2x4, warp tile 32x32, K chunk 64,
// 2-stage cp.async pipeline. 96KB smem -> 2 CTAs/SM.
#define AT_B  8192
#define BT_B  16384
#define STAGE_B (2*AT_B + 2*BT_B)     // 49152
#define OFF_AL  AT_B
#define OFF_BH  (2*AT_B)
#define OFF_BL  (2*AT_B + BT_B)
#define GSMEM (2*STAGE_B)             // 98304 bytes

__global__ __launch_bounds__(256, 2)
void mma_gemm_kernel(const __nv_bfloat16* __restrict__ Agh,
                     const __nv_bfloat16* __restrict__ Agl,
                     const __nv_bfloat16* __restrict__ Bgh,
                     const __nv_bfloat16* __restrict__ Bgl,
                     const float* __restrict__ bias, const float* __restrict__ res,
                     const float* __restrict__ lng, const float* __restrict__ lnb,
                     float* __restrict__ Cf,
                     __nv_bfloat16* __restrict__ Ch, __nv_bfloat16* __restrict__ Cl,
                     int Kt, int Nt, int relu, int split_ncols) {
    extern __shared__ __align__(16) char smem[];
    uint32_t smb = smem_u32(smem);
    int t   = threadIdx.x;
    int wid = t >> 5, lid = t & 31;
    int g   = lid >> 2, tg = lid & 3;
    int wm0 = (wid >> 2) * 32;           // 2 warp-rows (0,32)
    int wn0 = (wid & 3) * 32;            // 4 warp-cols
    int bn  = blockIdx.x << 7;
    int bm  = blockIdx.y << 6;           // BM = 64

    float acc[2][4][4];
    #pragma unroll
    for (int mt = 0; mt < 2; mt++)
        #pragma unroll
        for (int nt = 0; nt < 4; nt++)
            #pragma unroll
            for (int rr = 0; rr < 4; rr++) acc[mt][nt][rr] = 0.f;

    int nch = Kt >> 6;

    auto load_chunk = [&](int ch, int stg) {
        int k0 = ch << 6;
        uint32_t sb = smb + stg*STAGE_B;
        #pragma unroll
        for (int p = 0; p < 2; p++) {
            int seg = t + p*256;
            int row = seg >> 3, c16 = seg & 7;
            uint32_t sw = (uint32_t)(row*128) + (((uint32_t)(c16 ^ (row & 7))) << 4);
            const __nv_bfloat16* gh = Agh + (size_t)(bm + row)*Kt + k0 + c16*8;
            const __nv_bfloat16* gl = Agl + (size_t)(bm + row)*Kt + k0 + c16*8;
            cpa16(sb + sw, gh);
            cpa16(sb + OFF_AL + sw, gl);
        }
        #pragma unroll
        for (int p = 0; p < 4; p++) {
            int seg = t + p*256;
            int row = seg >> 3, c16 = seg & 7;
            uint32_t sw = (uint32_t)(row*128) + (((uint32_t)(c16 ^ (row & 7))) << 4);
            const __nv_bfloat16* gh = Bgh + (size_t)(bn + row)*Kt + k0 + c16*8;
            const __nv_bfloat16* gl = Bgl + (size_t)(bn + row)*Kt + k0 + c16*8;
            cpa16(sb + OFF_BH + sw, gh);
            cpa16(sb + OFF_BL + sw, gl);
        }
        asm volatile("cp.async.commit_group;" ::: "memory");
    };

    load_chunk(0, 0);
    for (int ch = 0; ch < nch; ch++) {
        if (ch + 1 < nch) {
            load_chunk(ch + 1, (ch + 1) & 1);
            asm volatile("cp.async.wait_group 1;" ::: "memory");
        } else {
            asm volatile("cp.async.wait_group 0;" ::: "memory");
        }
        __syncthreads();
        uint32_t sb = smb + (ch & 1)*STAGE_B;
        #pragma unroll
        for (int ks = 0; ks < 4; ks++) {
            uint32_t ah[2][4], al[2][4];
            int ac16 = ks*2 + (lid >> 4);
            #pragma unroll
            for (int mt = 0; mt < 2; mt++) {
                int row = wm0 + mt*16 + (lid & 15);
                uint32_t off = (uint32_t)(row*128) + (((uint32_t)(ac16 ^ (row & 7))) << 4);
                ldsm4(sb + off, ah[mt]);
                ldsm4(sb + OFF_AL + off, al[mt]);
            }
            int bc16 = ks*2 + ((lid >> 3) & 1);
            #pragma unroll
            for (int np = 0; np < 2; np++) {
                int row = wn0 + np*16 + ((lid >> 4) & 1)*8 + (lid & 7);
                uint32_t off = (uint32_t)(row*128) + (((uint32_t)(bc16 ^ (row & 7))) << 4);
                uint32_t bh4[4], bl4[4];
                ldsm4(sb + OFF_BH + off, bh4);
                ldsm4(sb + OFF_BL + off, bl4);
                #pragma unroll
                for (int half = 0; half < 2; half++) {
                    int nt = np*2 + half;
                    #pragma unroll
                    for (int mt = 0; mt < 2; mt++) {
                        mma16816(acc[mt][nt], ah[mt], bh4 + half*2);
                        mma16816(acc[mt][nt], ah[mt], bl4 + half*2);
                        mma16816(acc[mt][nt], al[mt], bh4 + half*2);
                    }
                }
            }
        }
        __syncthreads();
    }

    // ---------------- epilogue: bias / residual / relu ----------------
    #pragma unroll
    for (int nt = 0; nt < 4; nt++) {
        int colg = bn + wn0 + nt*8 + tg*2;
        float b0 = 0.f, b1 = 0.f;
        if (bias) { b0 = bias[colg]; b1 = bias[colg+1]; }
        #pragma unroll
        for (int mt = 0; mt < 2; mt++) {
            #pragma unroll
            for (int rp = 0; rp < 2; rp++) {
                int rowg = bm + wm0 + mt*16 + rp*8 + g;
                float v0 = acc[mt][nt][rp*2]   + b0;
                float v1 = acc[mt][nt][rp*2+1] + b1;
                if (res) {
                    float2 rv = *(const float2*)(res + (size_t)rowg*Nt + colg);
                    v0 += rv.x; v1 += rv.y;
                }
                if (relu) { v0 = fmaxf(v0, 0.f); v1 = fmaxf(v1, 0.f); }
                acc[mt][nt][rp*2]   = v0;
                acc[mt][nt][rp*2+1] = v1;
            }
        }
    }

    if (lng) {
        // LN over last dim; only used with Nt==128 (4 col-warps per row, 64 rows).
        float* rs = (float*)smem;        // [64][4]
        float* rq = rs + 256;            // [64][4]
        #pragma unroll
        for (int mt = 0; mt < 2; mt++) {
            #pragma unroll
            for (int rp = 0; rp < 2; rp++) {
                float s = 0.f, q = 0.f;
                #pragma unroll
                for (int nt = 0; nt < 4; nt++) {
                    float v0 = acc[mt][nt][rp*2], v1 = acc[mt][nt][rp*2+1];
                    s += v0 + v1;
                    q += v0*v0 + v1*v1;
                }
                s += __shfl_xor_sync(0xffffffffu, s, 1);
                s += __shfl_xor_sync(0xffffffffu, s, 2);
                q += __shfl_xor_sync(0xffffffffu, q, 1);
                q += __shfl_xor_sync(0xffffffffu, q, 2);
                if (tg == 0) {
                    int row = wm0 + mt*16 + rp*8 + g;
                    rs[row*4 + (wid & 3)] = s;
                    rq[row*4 + (wid & 3)] = q;
                }
            }
        }
        __syncthreads();
        #pragma unroll
        for (int mt = 0; mt < 2; mt++) {
            #pragma unroll
            for (int rp = 0; rp < 2; rp++) {
                int row = wm0 + mt*16 + rp*8 + g;
                float s = rs[row*4] + rs[row*4+1] + rs[row*4+2] + rs[row*4+3];
                float q = rq[row*4] + rq[row*4+1] + rq[row*4+2] + rq[row*4+3];
                float mean = s * 0.0078125f;
                float rstd = rsqrtf(q * 0.0078125f - mean*mean + 1e-5f);
                size_t rowoff = (size_t)(bm + row)*Nt;
                #pragma unroll
                for (int nt = 0; nt < 4; nt++) {
                    int col = wn0 + nt*8 + tg*2;
                    float2 gg = *(const float2*)(lng + col);
                    float2 gb = *(const float2*)(lnb + col);
                    float v0 = (acc[mt][nt][rp*2]   - mean)*rstd*gg.x + gb.x;
                    float v1 = (acc[mt][nt][rp*2+1] - mean)*rstd*gg.y + gb.y;
                    *(float2*)(Cf + rowoff + bn + col) = make_float2(v0, v1);
                    __nv_bfloat16 h0,l0,h1,l1;
                    bsplit(v0,h0,l0); bsplit(v1,h1,l1);
                    *(uint32_t*)(Ch + rowoff + bn + col) = pack2bf(h0,h1);
                    *(uint32_t*)(Cl + rowoff + bn + col) = pack2bf(l0,l1);
                }
            }
        }
    } else {
        #pragma unroll
        for (int mt = 0; mt < 2; mt++) {
            #pragma unroll
            for (int rp = 0; rp < 2; rp++) {
                int rowg = bm + wm0 + mt*16 + rp*8 + g;
                size_t rowoff = (size_t)rowg*Nt;
                #pragma unroll
                for (int nt = 0; nt < 4; nt++) {
                    int colg = bn + wn0 + nt*8 + tg*2;
                    float v0 = acc[mt][nt][rp*2], v1 = acc[mt][nt][rp*2+1];
                    if (Cf) *(float2*)(Cf + rowoff + colg) = make_float2(v0, v1);
                    if (Ch && colg < split_ncols) {
                        size_t so = (size_t)rowg*split_ncols + colg;
                        __nv_bfloat16 h0,l0,h1,l1;
                        bsplit(v0,h0,l0); bsplit(v1,h1,l1);
                        *(uint32_t*)(Ch + so) = pack2bf(h0,h1);
                        *(uint32_t*)(Cl + so) = pack2bf(l0,l1);
                    }
                }
            }
        }
    }
}

// ---------------- scores via split-bf16 MMA ----------------
// block = (b,h,l), 128 threads (4 warps, 2x2 of 32x32 tiles).
// s[b,h,i,l,j] = (1/SCALE) * q[i,:] . k[j,:]  (K=32), q/k from g_qk_h/l.
#define SC_T 80        // smem row stride bytes (16B-aligned, conflict-free)
__global__ __launch_bounds__(128)
void score_mma_kernel() {
    __shared__ __align__(16) char ssm[4*64*SC_T];   // 20480 B
    uint32_t smb = smem_u32(ssm);
    const uint32_t QH = 0, QL = 64*SC_T, KH = 2*64*SC_T, KL = 3*64*SC_T;
    int bid = blockIdx.x;
    int l = bid & 63, h = (bid >> 6) & 3, b = bid >> 8;
    int bh = b*HH + h;
    int t = threadIdx.x, wid = t >> 5, lid = t & 31;
    int g = lid >> 2, tg = lid & 3;
    int wm0 = (wid >> 1) * 32, wn0 = (wid & 1) * 32;

    #pragma unroll
    for (int p = 0; p < 2; p++) {
        int seg = t + p*128;              // 0..255
        int row = seg >> 2, c = seg & 3;
        uint32_t dst = (uint32_t)(row*SC_T + c*16);
        size_t qoff = ((size_t)((b*NN + row)*NN + l))*256 + h*DHH + c*8;
        size_t koff = ((size_t)((b*NN + l)*NN + row))*256 + 128 + h*DHH + c*8;
        cpa16(smb + QH + dst, g_qk_h + qoff);
        cpa16(smb + QL + dst, g_qk_l + qoff);
        cpa16(smb + KH + dst, g_qk_h + koff);
        cpa16(smb + KL + dst, g_qk_l + koff);
    }
    asm volatile("cp.async.commit_group;" ::: "memory");
    asm volatile("cp.async.wait_group 0;" ::: "memory");
    __syncthreads();

    float acc[2][4][4];
    #pragma unroll
    for (int mt = 0; mt < 2; mt++)
        #pragma unroll
        for (int nt = 0; nt < 4; nt++)
            #pragma unroll
            for (int rr = 0; rr < 4; rr++) acc[mt][nt][rr] = 0.f;

    #pragma unroll
    for (int ks = 0; ks < 2; ks++) {
        uint32_t ah[2][4], al[2][4];
        #pragma unroll
        for (int mt = 0; mt < 2; mt++) {
            uint32_t off = (uint32_t)((wm0 + mt*16 + (lid & 15))*SC_T
                                      + ks*32 + (lid >> 4)*16);
            ldsm4(smb + QH + off, ah[mt]);
            ldsm4(smb + QL + off, al[mt]);
        }
        #pragma unroll
        for (int np = 0; np < 2; np++) {
            int row = wn0 + np*16 + ((lid >> 4) & 1)*8 + (lid & 7);
            uint32_t off = (uint32_t)(row*SC_T + ks*32 + ((lid >> 3) & 1)*16);
            uint32_t bh4[4], bl4[4];
            ldsm4(smb + KH + off, bh4);
            ldsm4(smb + KL + off, bl4);
            #pragma unroll
            for (int half = 0; half < 2; half++) {
                int nt = np*2 + half;
                #pragma unroll
                for (int mt = 0; mt < 2; mt++) {
                    mma16816(acc[mt][nt], ah[mt], bh4 + half*2);
                    mma16816(acc[mt][nt], ah[mt], bl4 + half*2);
                    mma16816(acc[mt][nt], al[mt], bh4 + half*2);
                }
            }
        }
    }

    // write s[b][h][i][l][j]
    #pragma unroll
    for (int mt = 0; mt < 2; mt++) {
        #pragma unroll
        for (int rp = 0; rp < 2; rp++) {
            int i = wm0 + mt*16 + rp*8 + g;
            float* dst = g_s + ((size_t)(bh*NN + i)*NN + l)*NN;
            #pragma unroll
            for (int nt = 0; nt < 4; nt++) {
                int j = wn0 + nt*8 + tg*2;
                *(float2*)(dst + j) = make_float2(acc[mt][nt][rp*2]   * INV_SCALE,
                                                  acc[mt][nt][rp*2+1] * INV_SCALE);
            }
        }
    }
}

// ---------------- softmax over l on s[b][h][i][l][j] (contiguous tile) ------------
__global__ __launch_bounds__(256)
void softmax_kernel() {
    int bid = blockIdx.x;            // bh*64 + i
    size_t base = (size_t)bid * 4096;
    int t = threadIdx.x;
    int j = t & 63, lq = t >> 6;     // 4 l-groups of 16
    __shared__ float pm[4][64], ps[4][64];
    float v[16];
    float mx = -1e30f;
    #pragma unroll
    for (int u = 0; u < 16; u++) {
        v[u] = g_s[base + (size_t)(lq*16 + u)*64 + j];
        mx = fmaxf(mx, v[u]);
    }
    pm[lq][j] = mx;
    __syncthreads();
    mx = fmaxf(fmaxf(pm[0][j], pm[1][j]), fmaxf(pm[2][j], pm[3][j]));
    float s = 0.f;
    #pragma unroll
    for (int u = 0; u < 16; u++) { v[u] = __expf(v[u] - mx); s += v[u]; }
    ps[lq][j] = s;
    __syncthreads();
    float inv = 1.f / (ps[0][j] + ps[1][j] + ps[2][j] + ps[3][j]);
    #pragma unroll
    for (int u = 0; u < 16; u++)
        g_s[base + (size_t)(lq*16 + u)*64 + j] = v[u] * inv;
}

// ---------------- tiled attn_o (writes split bf16) ----------------
#define AT_V1 0                         // [i][l][36] floats
#define AT_V2 (16*16*36)                // [l][j][36]
#define AT_A  (2*16*16*36)              // [l][i][16]
#define ATTN_SMEM ((2*16*16*36 + 16*16*16)*4)

__global__ __launch_bounds__(256)
void attn_o_kernel() {
    extern __shared__ __align__(16) float sm[];
    float* v1s = sm + AT_V1;
    float* v2s = sm + AT_V2;
    float* as_ = sm + AT_A;
    int bx = blockIdx.x;
    int jt = bx & 3;
    int it = (bx >> 2) & 3;
    int h  = (bx >> 4) & 3;
    int b  = bx >> 6;
    int bh = b*HH + h;
    int i0 = it*16, j0 = jt*16;
    int t = threadIdx.x;
    int ti = t >> 4, tj = t & 15;

    float acc[32];
    #pragma unroll
    for (int d = 0; d < 32; d++) acc[d] = 0.f;

    for (int lc = 0; lc < 4; lc++) {
        int l0 = lc*16;
        #pragma unroll
        for (int k = 0; k < 8; k++) {
            int fid = t + k*256;
            int dq = fid & 7, l = (fid >> 3) & 15, i_ = fid >> 7;
            float4 v = *(const float4*)(g_qkv +
                ((size_t)((b*NN + i0 + i_)*NN + l0 + l))*512 + 256 + h*DHH + dq*4);
            *(float4*)(v1s + (i_*16 + l)*36 + dq*4) = v;
        }
        #pragma unroll
        for (int k = 0; k < 8; k++) {
            int fid = t + k*256;
            int dq = fid & 7, j_ = (fid >> 3) & 15, l_ = fid >> 7;
            float4 v = *(const float4*)(g_qkv +
                ((size_t)((b*NN + l0 + l_)*NN + j0 + j_))*512 + 384 + h*DHH + dq*4);
            *(float4*)(v2s + (l_*16 + j_)*36 + dq*4) = v;
        }
        #pragma unroll
        for (int k = 0; k < 4; k++) {
            int fid = t + k*256;
            int jq = fid & 3, i_ = (fid >> 2) & 15, l_ = fid >> 6;
            float4 v = *(const float4*)(g_s +
                ((size_t)(bh*NN + i0 + i_)*NN + l0 + l_)*NN + j0 + jq*4);
            *(float4*)(as_ + (l_*16 + i_)*16 + jq*4) = v;
        }
        __syncthreads();
        #pragma unroll 4
        for (int l = 0; l < 16; l++) {
            float a = as_[(l*16 + ti)*16 + tj];
            const float* p1 = v1s + (ti*16 + l)*36;
            const float* p2 = v2s + (l*16 + tj)*36;
            #pragma unroll
            for (int dq = 0; dq < 8; dq++) {
                float4 x = *(const float4*)(p1 + dq*4);
                float4 y = *(const float4*)(p2 + dq*4);
                acc[dq*4+0] = fmaf(a, x.x * y.x, acc[dq*4+0]);
                acc[dq*4+1] = fmaf(a, x.y * y.y, acc[dq*4+1]);
                acc[dq*4+2] = fmaf(a, x.z * y.z, acc[dq*4+2]);
                acc[dq*4+3] = fmaf(a, x.w * y.w, acc[dq*4+3]);
            }
        }
        __syncthreads();
    }
    size_t obase = ((size_t)((b*NN + i0 + ti)*NN + j0 + tj) << 7) + h*DHH;
    #pragma unroll
    for (int dq = 0; dq < 8; dq++) {
        __nv_bfloat16 h0,l0_,h1,l1,h2,l2,h3,l3;
        bsplit(acc[dq*4+0],h0,l0_); bsplit(acc[dq*4+1],h1,l1);
        bsplit(acc[dq*4+2],h2,l2);  bsplit(acc[dq*4+3],h3,l3);
        *(uint2*)(g_o_h + obase + dq*4) = make_uint2(pack2bf(h0,h1), pack2bf(h2,h3));
        *(uint2*)(g_o_l + obase + dq*4) = make_uint2(pack2bf(l0_,l1), pack2bf(l2,l3));
    }
}

// ---------------- final: out[b,n] = diag_tok . Wout + bout ----------------
__global__ __launch_bounds__(128)
void out_kernel(const float* __restrict__ Wout, const float* __restrict__ bout,
                float* __restrict__ out) {
    int bn = blockIdx.x;             // b*64 + n
    int n = bn & 63;
    int d = threadIdx.x;
    float v = g_tok[((size_t)bn*NN + n)*DD + d] * Wout[d];
    __shared__ float r[4];
    #pragma unroll
    for (int o = 16; o > 0; o >>= 1) v += __shfl_xor_sync(0xffffffffu, v, o);
    if ((d & 31) == 0) r[d >> 5] = v;
    __syncthreads();
    if (d == 0) out[bn] = r[0] + r[1] + r[2] + r[3] + bout[0];
}

// ---------------- host driver ----------------
extern "C" void kernel_launch(void* const* d_in, const int* in_sizes, int n_in,
                              void* d_out, int out_size) {
    const float* x    = (const float*)d_in[0];
    const float* ea   = (const float*)d_in[1];
    const void*  mask = d_in[2];
    const float* nW   = (const float*)d_in[3];
    const float* nb   = (const float*)d_in[4];
    const float* eW   = (const float*)d_in[5];
    const float* eb   = (const float*)d_in[6];
    const float* noe  = (const float*)d_in[7];
    const float* Wq   = (const float*)d_in[8];
    const float* Wk   = (const float*)d_in[9];
    const float* Wv1  = (const float*)d_in[10];
    const float* Wv2  = (const float*)d_in[11];
    const float* Wo   = (const float*)d_in[12];
    const float* bo   = (const float*)d_in[13];
    const float* ln1g = (const float*)d_in[14];
    const float* ln1b = (const float*)d_in[15];
    const float* W1   = (const float*)d_in[16];
    const float* b1   = (const float*)d_in[17];
    const float* W2   = (const float*)d_in[18];
    const float* b2   = (const float*)d_in[19];
    const float* ln2g = (const float*)d_in[20];
    const float* ln2b = (const float*)d_in[21];
    const float* Wout = (const float*)d_in[22];
    const float* bout = (const float*)d_in[23];

    float *tok, *qkv;
    __nv_bfloat16 *tokh, *tokl, *oh_, *ol_, *hidh, *hidl, *qkh, *qkl;
    __nv_bfloat16 *wqkvh, *wqkvl, *woh, *wol, *w1h, *w1l, *w2h, *w2l;
    cudaGetSymbolAddress((void**)&tok,   g_tok);
    cudaGetSymbolAddress((void**)&qkv,   g_qkv);
    cudaGetSymbolAddress((void**)&tokh,  g_tok_h);
    cudaGetSymbolAddress((void**)&tokl,  g_tok_l);
    cudaGetSymbolAddress((void**)&oh_,   g_o_h);
    cudaGetSymbolAddress((void**)&ol_,   g_o_l);
    cudaGetSymbolAddress((void**)&hidh,  g_hid_h);
    cudaGetSymbolAddress((void**)&hidl,  g_hid_l);
    cudaGetSymbolAddress((void**)&qkh,   g_qk_h);
    cudaGetSymbolAddress((void**)&qkl,   g_qk_l);
    cudaGetSymbolAddress((void**)&wqkvh, g_wqkvT_h);
    cudaGetSymbolAddress((void**)&wqkvl, g_wqkvT_l);
    cudaGetSymbolAddress((void**)&woh,   g_woT_h);
    cudaGetSymbolAddress((void**)&wol,   g_woT_l);
    cudaGetSymbolAddress((void**)&w1h,   g_w1T_h);
    cudaGetSymbolAddress((void**)&w1l,   g_w1T_l);
    cudaGetSymbolAddress((void**)&w2h,   g_w2T_h);
    cudaGetSymbolAddress((void**)&w2l,   g_w2T_l);

    cudaFuncSetAttribute(mma_gemm_kernel,
                         cudaFuncAttributeMaxDynamicSharedMemorySize, GSMEM);
    cudaFuncSetAttribute(attn_o_kernel,
                         cudaFuncAttributeMaxDynamicSharedMemorySize, ATTN_SMEM);

    detect_mask_kernel<<<1, 256>>>((const unsigned char*)mask);
    pack_all_kernel<<<2496, 256>>>(Wq, Wk, Wv1, Wv2, Wo, W1, W2,
                                   wqkvh, wqkvl, woh, wol, w1h, w1l, w2h, w2l);
    embed_kernel<<<MROWS, DD>>>(x, ea, mask, nW, nb, eW, eb, noe);

    dim3 gN128(1, MROWS/64);          // 512 blocks
    dim3 gN512(4, MROWS/64);          // 2048 blocks

    for (int l = 0; l < LL; l++) {
        const __nv_bfloat16* wqh = wqkvh + (size_t)l*512*128;
        const __nv_bfloat16* wql = wqkvl + (size_t)l*512*128;
        const __nv_bfloat16* wo_h = woh + (size_t)l*128*128;
        const __nv_bfloat16* wo_l = wol + (size_t)l*128*128;
        const __nv_bfloat16* w1_h = w1h + (size_t)l*512*128;
        const __nv_bfloat16* w1_l = w1l + (size_t)l*512*128;
        const __nv_bfloat16* w2_h = w2h + (size_t)l*128*512;
        const __nv_bfloat16* w2_l = w2l + (size_t)l*128*512;
        const float* bo_l  = bo  + (size_t)l*DD;
        const float* g1_l  = ln1g + (size_t)l*DD;
        const float* b1l_l = ln1b + (size_t)l*DD;
        const float* bf1_l = b1  + (size_t)l*FF;
        const float* bf2_l = b2  + (size_t)l*DD;
        const float* g2_l  = ln2g + (size_t)l*DD;
        const float* b2l_l = ln2b + (size_t)l*DD;

        // fused QKV projection: C = qkv fp32 + q|k split bf16 (cols 0..255)
        mma_gemm_kernel<<<gN512, 256, GSMEM>>>(tokh, tokl, wqh, wql,
            nullptr, nullptr, nullptr, nullptr, qkv, qkh, qkl, 128, 512, 0, 256);

        score_mma_kernel<<<BB*HH*NN, 128>>>();
        softmax_kernel<<<BB*HH*NN, 256>>>();
        attn_o_kernel<<<512, 256, ATTN_SMEM>>>();

        // o-projection + bias + residual(tok) + LN1 -> tok fp32 + split
        mma_gemm_kernel<<<gN128, 256, GSMEM>>>(oh_, ol_, wo_h, wo_l,
            bo_l, tok, g1_l, b1l_l, tok, tokh, tokl, 128, 128, 0, 128);
        // FFN up + relu -> hid split only
        mma_gemm_kernel<<<gN512, 256, GSMEM>>>(tokh, tokl, w1_h, w1_l,
            bf1_l, nullptr, nullptr, nullptr, nullptr, hidh, hidl, 128, 512, 1, 512);
        // FFN down + bias + residual(tok) + LN2 -> tok fp32 + split
        mma_gemm_kernel<<<gN128, 256, GSMEM>>>(hidh, hidl, w2_h, w2_l,
            bf2_l, tok, g2_l, b2l_l, tok, tokh, tokl, 512, 128, 0, 128);
    }

    out_kernel<<<BB*NN, 128>>>(Wout, bout, (float*)d_out);
}

// round 15
// speedup vs baseline: 1.1611x; 1.0271x over previous
#include <cuda_runtime.h>
#include <cuda_bf16.h>
#include <math.h>
#include <stdint.h>

// ---------------- problem constants ----------------
#define BB 8
#define NN 64
#define IN_DIM 16
#define EDGE_DIM 8
#define DD 128
#define HH 4
#define DHH 32
#define LL 3
#define FF 512
#define MROWS (BB*NN*NN)          // 32768
static const float INV_SCALE = 0.17677669529663687f; // 1/sqrt(32)

// ---------------- scratch (device globals; no runtime alloc) ----------------
__device__ float g_tok  [(size_t)MROWS*DD];
__device__ float g_v    [(size_t)MROWS*256];          // v1|v2 fp32 (compact)
__device__ float g_s    [(size_t)BB*HH*NN*NN*NN];     // [b][h][i][l][j]
// bf16 hi/lo activation copies (GEMM A operands)
__device__ __nv_bfloat16 g_tok_h[(size_t)MROWS*DD];
__device__ __nv_bfloat16 g_tok_l[(size_t)MROWS*DD];
__device__ __nv_bfloat16 g_o_h  [(size_t)MROWS*DD];
__device__ __nv_bfloat16 g_o_l  [(size_t)MROWS*DD];
__device__ __nv_bfloat16 g_hid_h[(size_t)MROWS*FF];
__device__ __nv_bfloat16 g_hid_l[(size_t)MROWS*FF];
// q|k split copies (cols 0..255 of qkv), stride 256
__device__ __nv_bfloat16 g_qk_h [(size_t)MROWS*256];
__device__ __nv_bfloat16 g_qk_l [(size_t)MROWS*256];
// transposed + bf16-split weights: layout [l][N][K]
__device__ __nv_bfloat16 g_wqkvT_h[(size_t)LL*512*128];
__device__ __nv_bfloat16 g_wqkvT_l[(size_t)LL*512*128];
__device__ __nv_bfloat16 g_woT_h  [(size_t)LL*128*128];
__device__ __nv_bfloat16 g_woT_l  [(size_t)LL*128*128];
__device__ __nv_bfloat16 g_w1T_h  [(size_t)LL*512*128];
__device__ __nv_bfloat16 g_w1T_l  [(size_t)LL*512*128];
__device__ __nv_bfloat16 g_w2T_h  [(size_t)LL*128*512];
__device__ __nv_bfloat16 g_w2T_l  [(size_t)LL*128*512];
__device__ int g_mask_mode;                            // 0=int32, 1=uint8, 2=float32

// ---------------- helpers ----------------
__device__ __forceinline__ void bsplit(float v, __nv_bfloat16& h, __nv_bfloat16& l) {
    h = __float2bfloat16(v);
    l = __float2bfloat16(v - __bfloat162float(h));
}
__device__ __forceinline__ uint32_t pack2bf(__nv_bfloat16 a, __nv_bfloat16 b) {
    return (uint32_t)__bfloat16_as_ushort(a) | ((uint32_t)__bfloat16_as_ushort(b) << 16);
}
__device__ __forceinline__ uint32_t smem_u32(const void* p) {
    uint32_t a;
    asm("{ .reg .u64 t; cvta.to.shared.u64 t, %1; cvt.u32.u64 %0, t; }" : "=r"(a) : "l"(p));
    return a;
}
// D += A*B  (m16n8k16, bf16 in, f32 acc)
__device__ __forceinline__ void mma16816(float* c, const uint32_t* a, const uint32_t* b) {
    asm volatile(
        "mma.sync.aligned.m16n8k16.row.col.f32.bf16.bf16.f32 "
        "{%0,%1,%2,%3}, {%4,%5,%6,%7}, {%8,%9}, {%0,%1,%2,%3};"
        : "+f"(c[0]), "+f"(c[1]), "+f"(c[2]), "+f"(c[3])
        : "r"(a[0]), "r"(a[1]), "r"(a[2]), "r"(a[3]), "r"(b[0]), "r"(b[1]));
}
__device__ __forceinline__ void ldsm4(uint32_t addr, uint32_t* r) {
    asm volatile("ldmatrix.sync.aligned.m8n8.x4.shared.b16 {%0,%1,%2,%3}, [%4];"
        : "=r"(r[0]), "=r"(r[1]), "=r"(r[2]), "=r"(r[3]) : "r"(addr));
}
__device__ __forceinline__ void cpa16(uint32_t saddr, const void* g) {
    asm volatile("cp.async.cg.shared.global [%0], [%1], 16;" :: "r"(saddr), "l"(g));
}

// ---------------- mask dtype detector ----------------
__global__ void detect_mask_kernel(const unsigned char* __restrict__ m) {
    __shared__ int has3f, hasodd;
    if (threadIdx.x == 0) { has3f = 0; hasodd = 0; }
    __syncthreads();
    for (int i = threadIdx.x; i < 4096; i += blockDim.x) {
        unsigned char v = m[i];
        if (v == 0x3F) atomicOr(&has3f, 1);
        if (v != 0 && (i & 3)) atomicOr(&hasodd, 1);
    }
    __syncthreads();
    if (threadIdx.x == 0) g_mask_mode = has3f ? 2 : (hasodd ? 1 : 0);
}

// ---------------- merged weight transpose + bf16 split ----------------
__global__ void pack_all_kernel(const float* __restrict__ Wq, const float* __restrict__ Wk,
                                const float* __restrict__ Wv1, const float* __restrict__ Wv2,
                                const float* __restrict__ Wo, const float* __restrict__ W1,
                                const float* __restrict__ W2,
                                __nv_bfloat16* __restrict__ qh, __nv_bfloat16* __restrict__ ql,
                                __nv_bfloat16* __restrict__ oh, __nv_bfloat16* __restrict__ ol,
                                __nv_bfloat16* __restrict__ h1, __nv_bfloat16* __restrict__ l1,
                                __nv_bfloat16* __restrict__ h2, __nv_bfloat16* __restrict__ l2) {
    int blk = blockIdx.x;
    const float* src; __nv_bfloat16 *dh, *dl;
    int K, N, dstN, nOff, idx;
    if (blk < 768) {
        int seg = blk / 192;
        idx = (blk - seg*192)*256 + threadIdx.x;
        src = (seg==0)?Wq:(seg==1)?Wk:(seg==2)?Wv1:Wv2;
        dh = qh; dl = ql; K = 128; N = 128; dstN = 512; nOff = seg*128;
    } else if (blk < 960) {
        idx = (blk-768)*256 + threadIdx.x;
        src = Wo; dh = oh; dl = ol; K = 128; N = 128; dstN = 128; nOff = 0;
    } else if (blk < 1728) {
        idx = (blk-960)*256 + threadIdx.x;
        src = W1; dh = h1; dl = l1; K = 128; N = 512; dstN = 512; nOff = 0;
    } else {
        idx = (blk-1728)*256 + threadIdx.x;
        src = W2; dh = h2; dl = l2; K = 512; N = 128; dstN = 128; nOff = 0;
    }
    if (idx >= LL*N*K) return;
    int k = idx % K;
    int n = (idx / K) % N;
    int ll = idx / (K*N);
    float v = src[((size_t)ll*K + k)*N + n];
    __nv_bfloat16 vh, vl; bsplit(v, vh, vl);
    size_t o = ((size_t)ll*dstN + nOff + n)*K + k;
    dh[o] = vh; dl[o] = vl;
}

// ---------------- embedding (fp32 + hi/lo) ----------------
__global__ void embed_kernel(const float* __restrict__ x,
                             const float* __restrict__ ea,
                             const void*  __restrict__ mask,
                             const float* __restrict__ nW, const float* __restrict__ nb,
                             const float* __restrict__ eW, const float* __restrict__ eb,
                             const float* __restrict__ noe) {
    int idx = blockIdx.x;                 // b*N*N + i*N + j
    int j = idx & 63;
    int i = (idx >> 6) & 63;
    int b = idx >> 12;
    int d = threadIdx.x;                  // 0..127
    __shared__ float sx[IN_DIM];
    __shared__ float se[EDGE_DIM];
    if (threadIdx.x < IN_DIM)  sx[threadIdx.x] = x[(b*NN + i)*IN_DIM + threadIdx.x];
    if (threadIdx.x < EDGE_DIM) se[threadIdx.x] = ea[((size_t)idx)*EDGE_DIM + threadIdx.x];
    __syncthreads();
    float v;
    if (i == j) {
        v = nb[d];
        #pragma unroll
        for (int e = 0; e < IN_DIM; e++) v = fmaf(sx[e], nW[e*DD + d], v);
    } else {
        bool m;
        int mm = g_mask_mode;
        if (mm == 0)      m = ((const int*)mask)[idx] != 0;
        else if (mm == 1) m = ((const unsigned char*)mask)[idx] != 0;
        else              m = ((const float*)mask)[idx] != 0.f;
        if (m) {
            v = eb[d];
            #pragma unroll
            for (int e = 0; e < EDGE_DIM; e++) v = fmaf(se[e], eW[e*DD + d], v);
        } else {
            v = noe[d];
        }
    }
    size_t off = (size_t)idx*DD + d;
    g_tok[off] = v;
    __nv_bfloat16 vh, vl; bsplit(v, vh, vl);
    g_tok_h[off] = vh; g_tok_l[off] = vl;
}

// ================= cp.async double-buffered mma.sync bf16 GEMM =================
// CTA tile 64x128, 256 threads, warp grid 2x4, warp tile 32x32, K chunk 64,
// 2-stage cp.async pipeline. 96KB smem -> 2 CTAs/SM.
// fp32 output written only for colg >= cf_off (compact stride Nt-cf_off).
#define AT_B  8192
#define BT_B  16384
#define STAGE_B (2*AT_B + 2*BT_B)     // 49152
#define OFF_AL  AT_B
#define OFF_BH  (2*AT_B)
#define OFF_BL  (2*AT_B + BT_B)
#define GSMEM (2*STAGE_B)             // 98304 bytes

__global__ __launch_bounds__(256, 2)
void mma_gemm_kernel(const __nv_bfloat16* __restrict__ Agh,
                     const __nv_bfloat16* __restrict__ Agl,
                     const __nv_bfloat16* __restrict__ Bgh,
                     const __nv_bfloat16* __restrict__ Bgl,
                     const float* __restrict__ bias, const float* __restrict__ res,
                     const float* __restrict__ lng, const float* __restrict__ lnb,
                     float* __restrict__ Cf,
                     __nv_bfloat16* __restrict__ Ch, __nv_bfloat16* __restrict__ Cl,
                     int Kt, int Nt, int relu, int split_ncols, int cf_off) {
    extern __shared__ __align__(16) char smem[];
    uint32_t smb = smem_u32(smem);
    int t   = threadIdx.x;
    int wid = t >> 5, lid = t & 31;
    int g   = lid >> 2, tg = lid & 3;
    int wm0 = (wid >> 2) * 32;           // 2 warp-rows (0,32)
    int wn0 = (wid & 3) * 32;            // 4 warp-cols
    int bn  = blockIdx.x << 7;
    int bm  = blockIdx.y << 6;           // BM = 64
    int cfN = Nt - cf_off;

    float acc[2][4][4];
    #pragma unroll
    for (int mt = 0; mt < 2; mt++)
        #pragma unroll
        for (int nt = 0; nt < 4; nt++)
            #pragma unroll
            for (int rr = 0; rr < 4; rr++) acc[mt][nt][rr] = 0.f;

    int nch = Kt >> 6;

    auto load_chunk = [&](int ch, int stg) {
        int k0 = ch << 6;
        uint32_t sb = smb + stg*STAGE_B;
        #pragma unroll
        for (int p = 0; p < 2; p++) {
            int seg = t + p*256;
            int row = seg >> 3, c16 = seg & 7;
            uint32_t sw = (uint32_t)(row*128) + (((uint32_t)(c16 ^ (row & 7))) << 4);
            const __nv_bfloat16* gh = Agh + (size_t)(bm + row)*Kt + k0 + c16*8;
            const __nv_bfloat16* gl = Agl + (size_t)(bm + row)*Kt + k0 + c16*8;
            cpa16(sb + sw, gh);
            cpa16(sb + OFF_AL + sw, gl);
        }
        #pragma unroll
        for (int p = 0; p < 4; p++) {
            int seg = t + p*256;
            int row = seg >> 3, c16 = seg & 7;
            uint32_t sw = (uint32_t)(row*128) + (((uint32_t)(c16 ^ (row & 7))) << 4);
            const __nv_bfloat16* gh = Bgh + (size_t)(bn + row)*Kt + k0 + c16*8;
            const __nv_bfloat16* gl = Bgl + (size_t)(bn + row)*Kt + k0 + c16*8;
            cpa16(sb + OFF_BH + sw, gh);
            cpa16(sb + OFF_BL + sw, gl);
        }
        asm volatile("cp.async.commit_group;" ::: "memory");
    };

    load_chunk(0, 0);
    for (int ch = 0; ch < nch; ch++) {
        if (ch + 1 < nch) {
            load_chunk(ch + 1, (ch + 1) & 1);
            asm volatile("cp.async.wait_group 1;" ::: "memory");
        } else {
            asm volatile("cp.async.wait_group 0;" ::: "memory");
        }
        __syncthreads();
        uint32_t sb = smb + (ch & 1)*STAGE_B;
        #pragma unroll
        for (int ks = 0; ks < 4; ks++) {
            uint32_t ah[2][4], al[2][4];
            int ac16 = ks*2 + (lid >> 4);
            #pragma unroll
            for (int mt = 0; mt < 2; mt++) {
                int row = wm0 + mt*16 + (lid & 15);
                uint32_t off = (uint32_t)(row*128) + (((uint32_t)(ac16 ^ (row & 7))) << 4);
                ldsm4(sb + off, ah[mt]);
                ldsm4(sb + OFF_AL + off, al[mt]);
            }
            int bc16 = ks*2 + ((lid >> 3) & 1);
            #pragma unroll
            for (int np = 0; np < 2; np++) {
                int row = wn0 + np*16 + ((lid >> 4) & 1)*8 + (lid & 7);
                uint32_t off = (uint32_t)(row*128) + (((uint32_t)(bc16 ^ (row & 7))) << 4);
                uint32_t bh4[4], bl4[4];
                ldsm4(sb + OFF_BH + off, bh4);
                ldsm4(sb + OFF_BL + off, bl4);
                #pragma unroll
                for (int half = 0; half < 2; half++) {
                    int nt = np*2 + half;
                    #pragma unroll
                    for (int mt = 0; mt < 2; mt++) {
                        mma16816(acc[mt][nt], ah[mt], bh4 + half*2);
                        mma16816(acc[mt][nt], ah[mt], bl4 + half*2);
                        mma16816(acc[mt][nt], al[mt], bh4 + half*2);
                    }
                }
            }
        }
        __syncthreads();
    }

    // ---------------- epilogue: bias / residual / relu ----------------
    #pragma unroll
    for (int nt = 0; nt < 4; nt++) {
        int colg = bn + wn0 + nt*8 + tg*2;
        float b0 = 0.f, b1 = 0.f;
        if (bias) { b0 = bias[colg]; b1 = bias[colg+1]; }
        #pragma unroll
        for (int mt = 0; mt < 2; mt++) {
            #pragma unroll
            for (int rp = 0; rp < 2; rp++) {
                int rowg = bm + wm0 + mt*16 + rp*8 + g;
                float v0 = acc[mt][nt][rp*2]   + b0;
                float v1 = acc[mt][nt][rp*2+1] + b1;
                if (res) {
                    float2 rv = *(const float2*)(res + (size_t)rowg*Nt + colg);
                    v0 += rv.x; v1 += rv.y;
                }
                if (relu) { v0 = fmaxf(v0, 0.f); v1 = fmaxf(v1, 0.f); }
                acc[mt][nt][rp*2]   = v0;
                acc[mt][nt][rp*2+1] = v1;
            }
        }
    }

    if (lng) {
        // LN over last dim; only used with Nt==128 (4 col-warps per row, 64 rows).
        float* rs = (float*)smem;        // [64][4]
        float* rq = rs + 256;            // [64][4]
        #pragma unroll
        for (int mt = 0; mt < 2; mt++) {
            #pragma unroll
            for (int rp = 0; rp < 2; rp++) {
                float s = 0.f, q = 0.f;
                #pragma unroll
                for (int nt = 0; nt < 4; nt++) {
                    float v0 = acc[mt][nt][rp*2], v1 = acc[mt][nt][rp*2+1];
                    s += v0 + v1;
                    q += v0*v0 + v1*v1;
                }
                s += __shfl_xor_sync(0xffffffffu, s, 1);
                s += __shfl_xor_sync(0xffffffffu, s, 2);
                q += __shfl_xor_sync(0xffffffffu, q, 1);
                q += __shfl_xor_sync(0xffffffffu, q, 2);
                if (tg == 0) {
                    int row = wm0 + mt*16 + rp*8 + g;
                    rs[row*4 + (wid & 3)] = s;
                    rq[row*4 + (wid & 3)] = q;
                }
            }
        }
        __syncthreads();
        #pragma unroll
        for (int mt = 0; mt < 2; mt++) {
            #pragma unroll
            for (int rp = 0; rp < 2; rp++) {
                int row = wm0 + mt*16 + rp*8 + g;
                float s = rs[row*4] + rs[row*4+1] + rs[row*4+2] + rs[row*4+3];
                float q = rq[row*4] + rq[row*4+1] + rq[row*4+2] + rq[row*4+3];
                float mean = s * 0.0078125f;
                float rstd = rsqrtf(q * 0.0078125f - mean*mean + 1e-5f);
                size_t rowoff = (size_t)(bm + row)*Nt;
                #pragma unroll
                for (int nt = 0; nt < 4; nt++) {
                    int col = wn0 + nt*8 + tg*2;
                    float2 gg = *(const float2*)(lng + col);
                    float2 gb = *(const float2*)(lnb + col);
                    float v0 = (acc[mt][nt][rp*2]   - mean)*rstd*gg.x + gb.x;
                    float v1 = (acc[mt][nt][rp*2+1] - mean)*rstd*gg.y + gb.y;
                    *(float2*)(Cf + rowoff + bn + col) = make_float2(v0, v1);
                    __nv_bfloat16 h0,l0,h1,l1;
                    bsplit(v0,h0,l0); bsplit(v1,h1,l1);
                    *(uint32_t*)(Ch + rowoff + bn + col) = pack2bf(h0,h1);
                    *(uint32_t*)(Cl + rowoff + bn + col) = pack2bf(l0,l1);
                }
            }
        }
    } else {
        #pragma unroll
        for (int mt = 0; mt < 2; mt++) {
            #pragma unroll
            for (int rp = 0; rp < 2; rp++) {
                int rowg = bm + wm0 + mt*16 + rp*8 + g;
                #pragma unroll
                for (int nt = 0; nt < 4; nt++) {
                    int colg = bn + wn0 + nt*8 + tg*2;
                    float v0 = acc[mt][nt][rp*2], v1 = acc[mt][nt][rp*2+1];
                    if (Cf && colg >= cf_off) {
                        *(float2*)(Cf + (size_t)rowg*cfN + (colg - cf_off)) =
                            make_float2(v0, v1);
                    }
                    if (Ch && colg < split_ncols) {
                        size_t so = (size_t)rowg*split_ncols + colg;
                        __nv_bfloat16 h0,l0,h1,l1;
                        bsplit(v0,h0,l0); bsplit(v1,h1,l1);
                        *(uint32_t*)(Ch + so) = pack2bf(h0,h1);
                        *(uint32_t*)(Cl + so) = pack2bf(l0,l1);
                    }
                }
            }
        }
    }
}

// ---------------- scores via split-bf16 MMA ----------------
// block = (b,h,l), 128 threads (4 warps, 2x2 of 32x32 tiles).
#define SC_T 80        // smem row stride bytes (16B-aligned, conflict-free)
__global__ __launch_bounds__(128)
void score_mma_kernel() {
    __shared__ __align__(16) char ssm[4*64*SC_T];   // 20480 B
    uint32_t smb = smem_u32(ssm);
    const uint32_t QH = 0, QL = 64*SC_T, KH = 2*64*SC_T, KL = 3*64*SC_T;
    int bid = blockIdx.x;
    int l = bid & 63, h = (bid >> 6) & 3, b = bid >> 8;
    int bh = b*HH + h;
    int t = threadIdx.x, wid = t >> 5, lid = t & 31;
    int g = lid >> 2, tg = lid & 3;
    int wm0 = (wid >> 1) * 32, wn0 = (wid & 1) * 32;

    #pragma unroll
    for (int p = 0; p < 2; p++) {
        int seg = t + p*128;              // 0..255
        int row = seg >> 2, c = seg & 3;
        uint32_t dst = (uint32_t)(row*SC_T + c*16);
        size_t qoff = ((size_t)((b*NN + row)*NN + l))*256 + h*DHH + c*8;
        size_t koff = ((size_t)((b*NN + l)*NN + row))*256 + 128 + h*DHH + c*8;
        cpa16(smb + QH + dst, g_qk_h + qoff);
        cpa16(smb + QL + dst, g_qk_l + qoff);
        cpa16(smb + KH + dst, g_qk_h + koff);
        cpa16(smb + KL + dst, g_qk_l + koff);
    }
    asm volatile("cp.async.commit_group;" ::: "memory");
    asm volatile("cp.async.wait_group 0;" ::: "memory");
    __syncthreads();

    float acc[2][4][4];
    #pragma unroll
    for (int mt = 0; mt < 2; mt++)
        #pragma unroll
        for (int nt = 0; nt < 4; nt++)
            #pragma unroll
            for (int rr = 0; rr < 4; rr++) acc[mt][nt][rr] = 0.f;

    #pragma unroll
    for (int ks = 0; ks < 2; ks++) {
        uint32_t ah[2][4], al[2][4];
        #pragma unroll
        for (int mt = 0; mt < 2; mt++) {
            uint32_t off = (uint32_t)((wm0 + mt*16 + (lid & 15))*SC_T
                                      + ks*32 + (lid >> 4)*16);
            ldsm4(smb + QH + off, ah[mt]);
            ldsm4(smb + QL + off, al[mt]);
        }
        #pragma unroll
        for (int np = 0; np < 2; np++) {
            int row = wn0 + np*16 + ((lid >> 4) & 1)*8 + (lid & 7);
            uint32_t off = (uint32_t)(row*SC_T + ks*32 + ((lid >> 3) & 1)*16);
            uint32_t bh4[4], bl4[4];
            ldsm4(smb + KH + off, bh4);
            ldsm4(smb + KL + off, bl4);
            #pragma unroll
            for (int half = 0; half < 2; half++) {
                int nt = np*2 + half;
                #pragma unroll
                for (int mt = 0; mt < 2; mt++) {
                    mma16816(acc[mt][nt], ah[mt], bh4 + half*2);
                    mma16816(acc[mt][nt], ah[mt], bl4 + half*2);
                    mma16816(acc[mt][nt], al[mt], bh4 + half*2);
                }
            }
        }
    }

    // write s[b][h][i][l][j]
    #pragma unroll
    for (int mt = 0; mt < 2; mt++) {
        #pragma unroll
        for (int rp = 0; rp < 2; rp++) {
            int i = wm0 + mt*16 + rp*8 + g;
            float* dst = g_s + ((size_t)(bh*NN + i)*NN + l)*NN;
            #pragma unroll
            for (int nt = 0; nt < 4; nt++) {
                int j = wn0 + nt*8 + tg*2;
                *(float2*)(dst + j) = make_float2(acc[mt][nt][rp*2]   * INV_SCALE,
                                                  acc[mt][nt][rp*2+1] * INV_SCALE);
            }
        }
    }
}

// ---------------- softmax over l on s[b][h][i][l][j] (contiguous tile) ------------
__global__ __launch_bounds__(256)
void softmax_kernel() {
    int bid = blockIdx.x;            // bh*64 + i
    size_t base = (size_t)bid * 4096;
    int t = threadIdx.x;
    int j = t & 63, lq = t >> 6;     // 4 l-groups of 16
    __shared__ float pm[4][64], ps[4][64];
    float v[16];
    float mx = -1e30f;
    #pragma unroll
    for (int u = 0; u < 16; u++) {
        v[u] = g_s[base + (size_t)(lq*16 + u)*64 + j];
        mx = fmaxf(mx, v[u]);
    }
    pm[lq][j] = mx;
    __syncthreads();
    mx = fmaxf(fmaxf(pm[0][j], pm[1][j]), fmaxf(pm[2][j], pm[3][j]));
    float s = 0.f;
    #pragma unroll
    for (int u = 0; u < 16; u++) { v[u] = __expf(v[u] - mx); s += v[u]; }
    ps[lq][j] = s;
    __syncthreads();
    float inv = 1.f / (ps[0][j] + ps[1][j] + ps[2][j] + ps[3][j]);
    #pragma unroll
    for (int u = 0; u < 16; u++)
        g_s[base + (size_t)(lq*16 + u)*64 + j] = v[u] * inv;
}

// ---------------- tiled attn_o (reads compact g_v, writes split bf16) --------------
#define AT_V1 0                         // [i][l][36] floats
#define AT_V2 (16*16*36)                // [l][j][36]
#define AT_A  (2*16*16*36)              // [l][i][16]
#define ATTN_SMEM ((2*16*16*36 + 16*16*16)*4)

__global__ __launch_bounds__(256)
void attn_o_kernel() {
    extern __shared__ __align__(16) float sm[];
    float* v1s = sm + AT_V1;
    float* v2s = sm + AT_V2;
    float* as_ = sm + AT_A;
    int bx = blockIdx.x;
    int jt = bx & 3;
    int it = (bx >> 2) & 3;
    int h  = (bx >> 4) & 3;
    int b  = bx >> 6;
    int bh = b*HH + h;
    int i0 = it*16, j0 = jt*16;
    int t = threadIdx.x;
    int ti = t >> 4, tj = t & 15;

    float acc[32];
    #pragma unroll
    for (int d = 0; d < 32; d++) acc[d] = 0.f;

    for (int lc = 0; lc < 4; lc++) {
        int l0 = lc*16;
        #pragma unroll
        for (int k = 0; k < 8; k++) {
            int fid = t + k*256;
            int dq = fid & 7, l = (fid >> 3) & 15, i_ = fid >> 7;
            float4 v = *(const float4*)(g_v +
                ((size_t)((b*NN + i0 + i_)*NN + l0 + l))*256 + h*DHH + dq*4);
            *(float4*)(v1s + (i_*16 + l)*36 + dq*4) = v;
        }
        #pragma unroll
        for (int k = 0; k < 8; k++) {
            int fid = t + k*256;
            int dq = fid & 7, j_ = (fid >> 3) & 15, l_ = fid >> 7;
            float4 v = *(const float4*)(g_v +
                ((size_t)((b*NN + l0 + l_)*NN + j0 + j_))*256 + 128 + h*DHH + dq*4);
            *(float4*)(v2s + (l_*16 + j_)*36 + dq*4) = v;
        }
        #pragma unroll
        for (int k = 0; k < 4; k++) {
            int fid = t + k*256;
            int jq = fid & 3, i_ = (fid >> 2) & 15, l_ = fid >> 6;
            float4 v = *(const float4*)(g_s +
                ((size_t)(bh*NN + i0 + i_)*NN + l0 + l_)*NN + j0 + jq*4);
            *(float4*)(as_ + (l_*16 + i_)*16 + jq*4) = v;
        }
        __syncthreads();
        #pragma unroll 4
        for (int l = 0; l < 16; l++) {
            float a = as_[(l*16 + ti)*16 + tj];
            const float* p1 = v1s + (ti*16 + l)*36;
            const float* p2 = v2s + (l*16 + tj)*36;
            #pragma unroll
            for (int dq = 0; dq < 8; dq++) {
                float4 x = *(const float4*)(p1 + dq*4);
                float4 y = *(const float4*)(p2 + dq*4);
                acc[dq*4+0] = fmaf(a, x.x * y.x, acc[dq*4+0]);
                acc[dq*4+1] = fmaf(a, x.y * y.y, acc[dq*4+1]);
                acc[dq*4+2] = fmaf(a, x.z * y.z, acc[dq*4+2]);
                acc[dq*4+3] = fmaf(a, x.w * y.w, acc[dq*4+3]);
            }
        }
        __syncthreads();
    }
    size_t obase = ((size_t)((b*NN + i0 + ti)*NN + j0 + tj) << 7) + h*DHH;
    #pragma unroll
    for (int dq = 0; dq < 8; dq++) {
        __nv_bfloat16 h0,l0_,h1,l1,h2,l2,h3,l3;
        bsplit(acc[dq*4+0],h0,l0_); bsplit(acc[dq*4+1],h1,l1);
        bsplit(acc[dq*4+2],h2,l2);  bsplit(acc[dq*4+3],h3,l3);
        *(uint2*)(g_o_h + obase + dq*4) = make_uint2(pack2bf(h0,h1), pack2bf(h2,h3));
        *(uint2*)(g_o_l + obase + dq*4) = make_uint2(pack2bf(l0_,l1), pack2bf(l2,l3));
    }
}

// ---------------- final: out[b,n] = diag_tok . Wout + bout ----------------
__global__ __launch_bounds__(128)
void out_kernel(const float* __restrict__ Wout, const float* __restrict__ bout,
                float* __restrict__ out) {
    int bn = blockIdx.x;             // b*64 + n
    int n = bn & 63;
    int d = threadIdx.x;
    float v = g_tok[((size_t)bn*NN + n)*DD + d] * Wout[d];
    __shared__ float r[4];
    #pragma unroll
    for (int o = 16; o > 0; o >>= 1) v += __shfl_xor_sync(0xffffffffu, v, o);
    if ((d & 31) == 0) r[d >> 5] = v;
    __syncthreads();
    if (d == 0) out[bn] = r[0] + r[1] + r[2] + r[3] + bout[0];
}

// ---------------- host driver ----------------
extern "C" void kernel_launch(void* const* d_in, const int* in_sizes, int n_in,
                              void* d_out, int out_size) {
    const float* x    = (const float*)d_in[0];
    const float* ea   = (const float*)d_in[1];
    const void*  mask = d_in[2];
    const float* nW   = (const float*)d_in[3];
    const float* nb   = (const float*)d_in[4];
    const float* eW   = (const float*)d_in[5];
    const float* eb   = (const float*)d_in[6];
    const float* noe  = (const float*)d_in[7];
    const float* Wq   = (const float*)d_in[8];
    const float* Wk   = (const float*)d_in[9];
    const float* Wv1  = (const float*)d_in[10];
    const float* Wv2  = (const float*)d_in[11];
    const float* Wo   = (const float*)d_in[12];
    const float* bo   = (const float*)d_in[13];
    const float* ln1g = (const float*)d_in[14];
    const float* ln1b = (const float*)d_in[15];
    const float* W1   = (const float*)d_in[16];
    const float* b1   = (const float*)d_in[17];
    const float* W2   = (const float*)d_in[18];
    const float* b2   = (const float*)d_in[19];
    const float* ln2g = (const float*)d_in[20];
    const float* ln2b = (const float*)d_in[21];
    const float* Wout = (const float*)d_in[22];
    const float* bout = (const float*)d_in[23];

    float *tok, *vbuf;
    __nv_bfloat16 *tokh, *tokl, *oh_, *ol_, *hidh, *hidl, *qkh, *qkl;
    __nv_bfloat16 *wqkvh, *wqkvl, *woh, *wol, *w1h, *w1l, *w2h, *w2l;
    cudaGetSymbolAddress((void**)&tok,   g_tok);
    cudaGetSymbolAddress((void**)&vbuf,  g_v);
    cudaGetSymbolAddress((void**)&tokh,  g_tok_h);
    cudaGetSymbolAddress((void**)&tokl,  g_tok_l);
    cudaGetSymbolAddress((void**)&oh_,   g_o_h);
    cudaGetSymbolAddress((void**)&ol_,   g_o_l);
    cudaGetSymbolAddress((void**)&hidh,  g_hid_h);
    cudaGetSymbolAddress((void**)&hidl,  g_hid_l);
    cudaGetSymbolAddress((void**)&qkh,   g_qk_h);
    cudaGetSymbolAddress((void**)&qkl,   g_qk_l);
    cudaGetSymbolAddress((void**)&wqkvh, g_wqkvT_h);
    cudaGetSymbolAddress((void**)&wqkvl, g_wqkvT_l);
    cudaGetSymbolAddress((void**)&woh,   g_woT_h);
    cudaGetSymbolAddress((void**)&wol,   g_woT_l);
    cudaGetSymbolAddress((void**)&w1h,   g_w1T_h);
    cudaGetSymbolAddress((void**)&w1l,   g_w1T_l);
    cudaGetSymbolAddress((void**)&w2h,   g_w2T_h);
    cudaGetSymbolAddress((void**)&w2l,   g_w2T_l);

    cudaFuncSetAttribute(mma_gemm_kernel,
                         cudaFuncAttributeMaxDynamicSharedMemorySize, GSMEM);
    cudaFuncSetAttribute(attn_o_kernel,
                         cudaFuncAttributeMaxDynamicSharedMemorySize, ATTN_SMEM);

    detect_mask_kernel<<<1, 256>>>((const unsigned char*)mask);
    pack_all_kernel<<<2496, 256>>>(Wq, Wk, Wv1, Wv2, Wo, W1, W2,
                                   wqkvh, wqkvl, woh, wol, w1h, w1l, w2h, w2l);
    embed_kernel<<<MROWS, DD>>>(x, ea, mask, nW, nb, eW, eb, noe);

    dim3 gN128(1, MROWS/64);          // 512 blocks
    dim3 gN512(4, MROWS/64);          // 2048 blocks

    for (int l = 0; l < LL; l++) {
        const __nv_bfloat16* wqh = wqkvh + (size_t)l*512*128;
        const __nv_bfloat16* wql = wqkvl + (size_t)l*512*128;
        const __nv_bfloat16* wo_h = woh + (size_t)l*128*128;
        const __nv_bfloat16* wo_l = wol + (size_t)l*128*128;
        const __nv_bfloat16* w1_h = w1h + (size_t)l*512*128;
        const __nv_bfloat16* w1_l = w1l + (size_t)l*512*128;
        const __nv_bfloat16* w2_h = w2h + (size_t)l*128*512;
        const __nv_bfloat16* w2_l = w2l + (size_t)l*128*512;
        const float* bo_l  = bo  + (size_t)l*DD;
        const float* g1_l  = ln1g + (size_t)l*DD;
        const float* b1l_l = ln1b + (size_t)l*DD;
        const float* bf1_l = b1  + (size_t)l*FF;
        const float* bf2_l = b2  + (size_t)l*DD;
        const float* g2_l  = ln2g + (size_t)l*DD;
        const float* b2l_l = ln2b + (size_t)l*DD;

        // fused QKV projection: q|k -> split bf16 only (cols<256);
        // v1|v2 -> compact fp32 g_v (cols>=256)
        mma_gemm_kernel<<<gN512, 256, GSMEM>>>(tokh, tokl, wqh, wql,
            nullptr, nullptr, nullptr, nullptr, vbuf, qkh, qkl, 128, 512, 0, 256, 256);

        score_mma_kernel<<<BB*HH*NN, 128>>>();
        softmax_kernel<<<BB*HH*NN, 256>>>();
        attn_o_kernel<<<512, 256, ATTN_SMEM>>>();

        // o-projection + bias + residual(tok) + LN1 -> tok fp32 + split
        mma_gemm_kernel<<<gN128, 256, GSMEM>>>(oh_, ol_, wo_h, wo_l,
            bo_l, tok, g1_l, b1l_l, tok, tokh, tokl, 128, 128, 0, 128, 0);
        // FFN up + relu -> hid split only
        mma_gemm_kernel<<<gN512, 256, GSMEM>>>(tokh, tokl, w1_h, w1_l,
            bf1_l, nullptr, nullptr, nullptr, nullptr, hidh, hidl, 128, 512, 1, 512, 0);
        // FFN down + bias + residual(tok) + LN2 -> tok fp32 + split
        mma_gemm_kernel<<<gN128, 256, GSMEM>>>(hidh, hidl, w2_h, w2_l,
            bf2_l, tok, g2_l, b2l_l, tok, tokh, tokl, 512, 128, 0, 128, 0);
    }

    out_kernel<<<BB*NN, 128>>>(Wout, bout, (float*)d_out);
}